// round 10
// baseline (speedup 1.0000x reference)
#include <cuda_runtime.h>
#include <cuda_bf16.h>
#include <math.h>
#include <stdint.h>

// Problem constants
#define B_    4
#define T_    2048
#define C_    2048
#define NH_   16
#define NKV_  8
#define HD_   128
#define M_    (B_*T_)          // 8192
#define KVD_  (NKV_*HD_)       // 1024
#define QKVN  (C_ + 2*KVD_)    // 4096 fused projection width

// ---------------- scratch ----------------------------------------------------
__device__ float g_qkv[(size_t)M_ * QKVN];   // fused QKV output
__device__ float g_vt[(size_t)B_ * NKV_ * HD_ * T_]; // V transposed, tf32
__device__ float g_o[(size_t)M_ * C_];       // attention out (tf32-rounded)
__device__ float g_xr[(size_t)M_ * C_];      // x rounded to tf32
__device__ float g_wqkv[(size_t)QKVN * C_];  // concat rounded Wq|Wk|Wv
__device__ float g_wor[(size_t)C_ * C_];

// ---------------- helpers ----------------------------------------------------
__device__ __forceinline__ float to_tf32(float x) {
    uint32_t u;
    asm("cvt.rna.tf32.f32 %0, %1;" : "=r"(u) : "f"(x));
    return __uint_as_float(u);
}

__device__ __forceinline__ void cp_async16(void* smem, const void* gmem) {
    uint32_t sa = (uint32_t)__cvta_generic_to_shared(smem);
    asm volatile("cp.async.cg.shared.global [%0], [%1], 16;\n" :: "r"(sa), "l"(gmem));
}
#define CP_COMMIT() asm volatile("cp.async.commit_group;\n" ::: "memory")
#define CP_WAIT(n)  asm volatile("cp.async.wait_group %0;\n" :: "n"(n) : "memory")

#define MMA_TF32(d, a, b) \
    asm volatile("mma.sync.aligned.m16n8k8.row.col.f32.tf32.tf32.f32 " \
                 "{%0,%1,%2,%3}, {%4,%5,%6,%7}, {%8,%9}, {%0,%1,%2,%3};" \
                 : "+f"(d[0]), "+f"(d[1]), "+f"(d[2]), "+f"(d[3]) \
                 : "r"(a[0]), "r"(a[1]), "r"(a[2]), "r"(a[3]), "r"(b[0]), "r"(b[1]))

// ldmatrix x4: one call = 4 8x4-tf32 tiles; per-thread address = row pointer.
__device__ __forceinline__ void ldsm4(uint32_t* r, const float* p) {
    uint32_t a = (uint32_t)__cvta_generic_to_shared(p);
    asm volatile("ldmatrix.sync.aligned.m8n8.x4.shared.b16 {%0,%1,%2,%3}, [%4];"
                 : "=r"(r[0]), "=r"(r[1]), "=r"(r[2]), "=r"(r[3]) : "r"(a));
}

// ---------------- fused tf32 rounding pass (MLP=4 per thread) ----------------
__global__ void round_all_kernel(const float* __restrict__ x,  const float* __restrict__ Wq,
                                 const float* __restrict__ Wk, const float* __restrict__ Wv,
                                 const float* __restrict__ Wo,
                                 float* __restrict__ xr, float* __restrict__ wqkv,
                                 float* __restrict__ wor) {
    const size_t NX = (size_t)M_ * C_ / 4;
    const size_t NQ = (size_t)C_ * C_ / 4;
    const size_t NK = (size_t)KVD_ * C_ / 4;
    size_t j = ((size_t)blockIdx.x * blockDim.x + threadIdx.x) * 4; // float4 index
    const float4* src; float4* dst; size_t off;
    if (j < NX)                    { src = (const float4*)x;  dst = (float4*)xr;   off = j; }
    else if (j < NX + NQ)          { src = (const float4*)Wq; dst = (float4*)wqkv; off = j - NX; }
    else if (j < NX + NQ + NK)     { src = (const float4*)Wk; dst = (float4*)(wqkv + (size_t)C_ * C_); off = j - NX - NQ; }
    else if (j < NX + NQ + 2*NK)   { src = (const float4*)Wv; dst = (float4*)(wqkv + (size_t)(C_ + KVD_) * C_); off = j - NX - NQ - NK; }
    else if (j < NX + 2*NQ + 2*NK) { src = (const float4*)Wo; dst = (float4*)wor;  off = j - NX - NQ - 2*NK; }
    else return;
    float4 v0 = src[off], v1 = src[off + 1], v2 = src[off + 2], v3 = src[off + 3];
    v0.x = to_tf32(v0.x); v0.y = to_tf32(v0.y); v0.z = to_tf32(v0.z); v0.w = to_tf32(v0.w);
    v1.x = to_tf32(v1.x); v1.y = to_tf32(v1.y); v1.z = to_tf32(v1.z); v1.w = to_tf32(v1.w);
    v2.x = to_tf32(v2.x); v2.y = to_tf32(v2.y); v2.z = to_tf32(v2.z); v2.w = to_tf32(v2.w);
    v3.x = to_tf32(v3.x); v3.y = to_tf32(v3.y); v3.z = to_tf32(v3.z); v3.w = to_tf32(v3.w);
    dst[off] = v0; dst[off + 1] = v1; dst[off + 2] = v2; dst[off + 3] = v3;
}
#define ROUND_TOTAL4 ((size_t)M_*C_/4 + 2*((size_t)C_*C_/4) + 2*((size_t)KVD_*C_/4))

// ---------------- tf32 tensor-core GEMM: C[M,N] = A[M,K] * B[N,K]^T ----------
#define TBM 128
#define TBN 128
#define TBK 32
#define TSTR 36
#define GEMM_SMEM_BYTES (2 * (TBM * TSTR + TBN * TSTR) * 4)   // 73728

__global__ void __launch_bounds__(256, 2) gemm_tf32(const float* __restrict__ A,
                                                    const float* __restrict__ Bm,
                                                    float* __restrict__ Cm,
                                                    int M, int N, int K) {
    extern __shared__ float sm[];
    float* As = sm;
    float* Bs = sm + 2 * TBM * TSTR;

    const int tid = threadIdx.x;
    const int wid = tid >> 5;
    const int lane = tid & 31;
    const int warp_m = wid >> 2;
    const int warp_n = wid & 3;
    const int g = lane >> 2;
    const int t = lane & 3;

    const int rowA  = lane & 15;
    const int koffA = (lane >> 4) * 4;
    const int rowB  = (lane & 7) + ((lane >> 4) << 3);
    const int koffB = ((lane >> 3) & 1) * 4;

    const float* Ag = A + (size_t)blockIdx.y * TBM * K;
    const float* Bg = Bm + (size_t)blockIdx.x * TBN * K;

    float c[4][4][4];
#pragma unroll
    for (int mt = 0; mt < 4; mt++)
#pragma unroll
        for (int nt = 0; nt < 4; nt++)
#pragma unroll
            for (int r = 0; r < 4; r++) c[mt][nt][r] = 0.f;

    auto load_tile = [&](int it, int buf) {
        int k0 = it * TBK;
        float* as = As + buf * TBM * TSTR;
        float* bs = Bs + buf * TBN * TSTR;
#pragma unroll
        for (int i = 0; i < 4; i++) {
            int v = tid + i * 256;
            int r = v >> 3;
            int c4 = (v & 7) * 4;
            cp_async16(as + r * TSTR + c4, Ag + (size_t)r * K + k0 + c4);
            cp_async16(bs + r * TSTR + c4, Bg + (size_t)r * K + k0 + c4);
        }
    };

    const int NIT = K / TBK;
    load_tile(0, 0);
    CP_COMMIT();

    for (int it = 0; it < NIT; ++it) {
        int cur = it & 1;
        if (it + 1 < NIT) {
            load_tile(it + 1, cur ^ 1);
            CP_COMMIT();
            CP_WAIT(1);
        } else {
            CP_WAIT(0);
        }
        __syncthreads();

        const float* as = As + cur * TBM * TSTR;
        const float* bs = Bs + cur * TBN * TSTR;

#pragma unroll
        for (int kk = 0; kk < TBK; kk += 8) {
            uint32_t af[4][4], bf4[2][4];
#pragma unroll
            for (int mt = 0; mt < 4; mt++)
                ldsm4(af[mt], as + (warp_m * 64 + mt * 16 + rowA) * TSTR + kk + koffA);
#pragma unroll
            for (int np = 0; np < 2; np++)
                ldsm4(bf4[np], bs + (warp_n * 32 + np * 16 + rowB) * TSTR + kk + koffB);
#pragma unroll
            for (int mt = 0; mt < 4; mt++)
#pragma unroll
                for (int nt = 0; nt < 4; nt++)
                    MMA_TF32(c[mt][nt], af[mt], (&bf4[nt >> 1][(nt & 1) * 2]));
        }
        __syncthreads();
    }

    const int row_base = blockIdx.y * TBM + warp_m * 64;
    const int col_base = blockIdx.x * TBN + warp_n * 32;
#pragma unroll
    for (int mt = 0; mt < 4; mt++) {
#pragma unroll
        for (int nt = 0; nt < 4; nt++) {
            int row = row_base + mt * 16 + g;
            int col = col_base + nt * 8 + 2 * t;
            *(float2*)(Cm + (size_t)row * N + col)       = make_float2(c[mt][nt][0], c[mt][nt][1]);
            *(float2*)(Cm + (size_t)(row + 8) * N + col) = make_float2(c[mt][nt][2], c[mt][nt][3]);
        }
    }
}

// ---------------- RoPE on fused qkv (in place; outputs tf32-rounded) ---------
__global__ void rope_kernel(float* __restrict__ qkv, int col_off, int nheads, int total_pairs) {
    int idx = blockIdx.x * blockDim.x + threadIdx.x;
    if (idx >= total_pairs) return;
    int d   = idx & 63;
    int tmp = idx >> 6;
    int h   = tmp % nheads;
    int bt  = tmp / nheads;
    int t   = bt & (T_ - 1);

    float* base = qkv + (size_t)bt * QKVN + col_off + h * HD_;
    float x1 = base[d];
    float x2 = base[d + 64];

    int i1 = d >> 1;
    const float L2C = 0.20762050593046f; // log2(10000)/64
    float inv1 = exp2f(-(float)i1 * L2C);
    float inv2 = exp2f(-(float)(i1 + 32) * L2C);
    float a1 = (float)t * inv1;
    float a2 = (float)t * inv2;
    float s1, c1, s2, c2;
    sincosf(a1, &s1, &c1);
    sincosf(a2, &s2, &c2);

    base[d]      = to_tf32(x1 * c1 - x2 * s1);
    base[d + 64] = to_tf32(x2 * c2 + x1 * s2);
}

// ---------------- V transpose: qkv V cols -> (b,kvh,hd,t), tf32-rounded ------
__global__ void vtrans_kernel(const float* __restrict__ qkv, float* __restrict__ Vt) {
    __shared__ float tile[32][33];
    const int z = blockIdx.z;
    const int b = z / NKV_;
    const int kvh = z % NKV_;
    const int t0 = blockIdx.x * 32;
    const int h0 = blockIdx.y * 32;

#pragma unroll
    for (int i = 0; i < 4; i++) {
        int tt = t0 + threadIdx.y + i * 8;
        tile[threadIdx.y + i * 8][threadIdx.x] =
            qkv[(size_t)(b * T_ + tt) * QKVN + C_ + KVD_ + kvh * HD_ + h0 + threadIdx.x];
    }
    __syncthreads();
#pragma unroll
    for (int i = 0; i < 4; i++) {
        int hd = h0 + threadIdx.y + i * 8;
        int tt = t0 + threadIdx.x;
        Vt[((size_t)(b * NKV_ + kvh) * HD_ + hd) * T_ + tt] =
            to_tf32(tile[threadIdx.x][threadIdx.y + i * 8]);
    }
}

// ---------------- Flash attention (tf32 TC, 128x64 tiles, 512 threads) -------
#define ABM 128
#define ABN 64
#define AQST 132          // Q/K tile row stride
#define AVST 68           // Vt tile row stride
#define ASST 68           // S/P tile row stride
#define ATT_THREADS 512

#define ATT_SMEM_FLOATS (ABM*AQST + 2*ABN*AQST + HD_*AVST + ABM*ASST + 3*ABM)
#define ATT_SMEM_BYTES  (ATT_SMEM_FLOATS * 4)   // 206336

__global__ void __launch_bounds__(ATT_THREADS, 1) attn_kernel(const float* __restrict__ QKV,
                                                              const float* __restrict__ Vt,
                                                              float* __restrict__ O) {
    const int qt  = (int)gridDim.x - 1 - (int)blockIdx.x; // big tiles first
    const int h   = blockIdx.y;
    const int b   = blockIdx.z;
    const int kvh = h >> 1;

    extern __shared__ float sm[];
    float* Qs  = sm;                            // [128][132]
    float* Ks  = Qs + ABM * AQST;               // [2][64][132]
    float* Vs  = Ks + 2 * ABN * AQST;           // [128][68]
    float* Ss  = Vs + HD_ * AVST;               // [128][68]
    float* Ms  = Ss + ABM * ASST;
    float* Ls  = Ms + ABM;
    float* Al  = Ls + ABM;

    const int tid  = threadIdx.x;
    const int wid  = tid >> 5;
    const int lane = tid & 31;
    const int warp_m = wid & 3;                 // 0..3 -> 32-row band
    const int warp_n = wid >> 2;                // 0..3
    const int g = lane >> 2;
    const int t = lane & 3;
    const int rband = warp_m * 32;
    const int scol0 = warp_n * 16;              // S cols (16 per warp)
    const int ocol0 = warp_n * 32;              // O cols (32 per warp)

    // ldmatrix per-thread offsets
    const int rowA  = lane & 15;
    const int koffA = (lane >> 4) * 4;
    const int rowB  = (lane & 7) + ((lane >> 4) << 3);
    const int koffB = ((lane >> 3) & 1) * 4;

    const int q0 = qt * ABM;
    const int jtmax = 2 * qt + 1;
    const float* vtb = Vt + (size_t)(b * NKV_ + kvh) * HD_ * T_;
    const float* qb  = QKV + (size_t)(b * T_ + q0) * QKVN + h * HD_;
    const float* kb  = QKV + (size_t)(b * T_) * QKVN + C_ + kvh * HD_;

    // preload Q tile
    for (int l = tid; l < ABM * 32; l += ATT_THREADS) {
        int r = l >> 5;
        int c = (l & 31) * 4;
        *(float4*)(Qs + r * AQST + c) = *(const float4*)(qb + (size_t)r * QKVN + c);
    }
    if (tid < ABM) { Ms[tid] = -1e30f; Ls[tid] = 0.f; }

    auto load_k = [&](int jt, int buf) {
        const int j0 = jt * ABN;
        float* ks = Ks + buf * ABN * AQST;
#pragma unroll
        for (int i = 0; i < 4; i++) {
            int v = i * ATT_THREADS + tid;
            int r = v >> 5;
            int c4 = (v & 31) * 4;
            cp_async16(ks + r * AQST + c4, kb + (size_t)(j0 + r) * QKVN + c4);
        }
    };
    auto load_v = [&](int jt) {
        const int j0 = jt * ABN;
#pragma unroll
        for (int i = 0; i < 4; i++) {
            int v = i * ATT_THREADS + tid;
            int r = v >> 4;
            int c4 = (v & 15) * 4;
            cp_async16(Vs + r * AVST + c4, vtb + (size_t)r * T_ + j0 + c4);
        }
    };

    float o[2][4][4];
#pragma unroll
    for (int mt = 0; mt < 2; mt++)
#pragma unroll
        for (int nt = 0; nt < 4; nt++)
#pragma unroll
            for (int r = 0; r < 4; r++) o[mt][nt][r] = 0.f;

    load_k(0, 0);
    CP_COMMIT();
    __syncthreads();

    const float scale = 0.08838834764831845f; // 1/sqrt(128)

    for (int jt = 0; jt <= jtmax; jt++) {
        const int cur = jt & 1;
        load_v(jt);
        CP_COMMIT();
        if (jt < jtmax) {
            load_k(jt + 1, cur ^ 1);
            CP_COMMIT();
            CP_WAIT(2);
        } else {
            CP_WAIT(1);
        }
        __syncthreads();

        // ---- S = Q K^T : per warp 32 rows x 16 cols ----
        const float* ksf = Ks + cur * ABN * AQST;
        float s[2][2][4];
#pragma unroll
        for (int mt = 0; mt < 2; mt++)
#pragma unroll
            for (int nt = 0; nt < 2; nt++)
#pragma unroll
                for (int r = 0; r < 4; r++) s[mt][nt][r] = 0.f;

#pragma unroll
        for (int kk = 0; kk < HD_; kk += 8) {
            uint32_t af[2][4], bf4[4];
#pragma unroll
            for (int mt = 0; mt < 2; mt++)
                ldsm4(af[mt], Qs + (rband + mt * 16 + rowA) * AQST + kk + koffA);
            ldsm4(bf4, ksf + (scol0 + rowB) * AQST + kk + koffB);
#pragma unroll
            for (int mt = 0; mt < 2; mt++)
#pragma unroll
                for (int nt = 0; nt < 2; nt++)
                    MMA_TF32(s[mt][nt], af[mt], (&bf4[nt * 2]));
        }

        // ---- scale + causal mask + store ----
        const bool diag = (jt >= 2 * qt);
#pragma unroll
        for (int mt = 0; mt < 2; mt++) {
#pragma unroll
            for (int nt = 0; nt < 2; nt++) {
                int c0 = scol0 + nt * 8 + 2 * t;
                int rlo = rband + mt * 16 + g, rhi = rlo + 8;
                float v0 = s[mt][nt][0] * scale, v1 = s[mt][nt][1] * scale;
                float v2 = s[mt][nt][2] * scale, v3 = s[mt][nt][3] * scale;
                if (diag) {
                    int gc0 = jt * ABN + c0;
                    if (gc0     > q0 + rlo) v0 = -1e30f;
                    if (gc0 + 1 > q0 + rlo) v1 = -1e30f;
                    if (gc0     > q0 + rhi) v2 = -1e30f;
                    if (gc0 + 1 > q0 + rhi) v3 = -1e30f;
                }
                *(float2*)(Ss + rlo * ASST + c0) = make_float2(v0, v1);
                *(float2*)(Ss + rhi * ASST + c0) = make_float2(v2, v3);
            }
        }
        __syncthreads();

        // ---- online softmax: 4 threads per row, 16 cols each ----
        {
            int row = tid >> 2;
            int q4 = tid & 3;
            float mprev = Ms[row];
            float mx = -1e30f;
#pragma unroll
            for (int i = 0; i < 16; i++)
                mx = fmaxf(mx, Ss[row * ASST + q4 + 4 * i]);
            mx = fmaxf(mx, __shfl_xor_sync(0xffffffffu, mx, 1));
            mx = fmaxf(mx, __shfl_xor_sync(0xffffffffu, mx, 2));
            mx = fmaxf(mx, mprev);
            float sum = 0.f;
#pragma unroll
            for (int i = 0; i < 16; i++) {
                float p = to_tf32(__expf(Ss[row * ASST + q4 + 4 * i] - mx));
                Ss[row * ASST + q4 + 4 * i] = p;
                sum += p;
            }
            sum += __shfl_xor_sync(0xffffffffu, sum, 1);
            sum += __shfl_xor_sync(0xffffffffu, sum, 2);
            if (q4 == 0) {
                float alpha = __expf(mprev - mx);
                Ms[row] = mx;
                Ls[row] = Ls[row] * alpha + sum;
                Al[row] = alpha;
            }
        }
        if (jt < jtmax) { CP_WAIT(1); } else { CP_WAIT(0); }
        __syncthreads();

        // ---- O = alpha*O + P @ V : per warp 32 rows x 32 hd-cols ----
        {
#pragma unroll
            for (int mt = 0; mt < 2; mt++) {
                float al_lo = Al[rband + mt * 16 + g];
                float al_hi = Al[rband + mt * 16 + 8 + g];
#pragma unroll
                for (int nt = 0; nt < 4; nt++) {
                    o[mt][nt][0] *= al_lo; o[mt][nt][1] *= al_lo;
                    o[mt][nt][2] *= al_hi; o[mt][nt][3] *= al_hi;
                }
            }
#pragma unroll
            for (int kk = 0; kk < ABN; kk += 8) {
                uint32_t af[2][4], bf4[2][4];
#pragma unroll
                for (int mt = 0; mt < 2; mt++)
                    ldsm4(af[mt], Ss + (rband + mt * 16 + rowA) * ASST + kk + koffA);
#pragma unroll
                for (int np = 0; np < 2; np++)
                    ldsm4(bf4[np], Vs + (ocol0 + np * 16 + rowB) * AVST + kk + koffB);
#pragma unroll
                for (int mt = 0; mt < 2; mt++)
#pragma unroll
                    for (int nt = 0; nt < 4; nt++)
                        MMA_TF32(o[mt][nt], af[mt], (&bf4[nt >> 1][(nt & 1) * 2]));
            }
        }
        __syncthreads();
    }

    // ---- epilogue ----
#pragma unroll
    for (int mt = 0; mt < 2; mt++) {
        int rlo = rband + mt * 16 + g, rhi = rlo + 8;
        float inv_lo = 1.f / Ls[rlo];
        float inv_hi = 1.f / Ls[rhi];
        float* dlo = O + ((size_t)(b * T_ + q0 + rlo) * NH_ + h) * HD_;
        float* dhi = O + ((size_t)(b * T_ + q0 + rhi) * NH_ + h) * HD_;
#pragma unroll
        for (int nt = 0; nt < 4; nt++) {
            int col = ocol0 + nt * 8 + 2 * t;
            *(float2*)(dlo + col) = make_float2(to_tf32(o[mt][nt][0] * inv_lo),
                                                to_tf32(o[mt][nt][1] * inv_lo));
            *(float2*)(dhi + col) = make_float2(to_tf32(o[mt][nt][2] * inv_hi),
                                                to_tf32(o[mt][nt][3] * inv_hi));
        }
    }
}

// ---------------- launch ------------------------------------------------------
extern "C" void kernel_launch(void* const* d_in, const int* in_sizes, int n_in,
                              void* d_out, int out_size) {
    const float* x  = (const float*)d_in[0];
    const float* Wq = (const float*)d_in[1];
    const float* Wk = (const float*)d_in[2];
    const float* Wv = (const float*)d_in[3];
    const float* Wo = (const float*)d_in[4];
    float* y = (float*)d_out;

    float *qkv, *vt, *o, *xr, *wqkv, *wor;
    cudaGetSymbolAddress((void**)&qkv, g_qkv);
    cudaGetSymbolAddress((void**)&vt,  g_vt);
    cudaGetSymbolAddress((void**)&o,   g_o);
    cudaGetSymbolAddress((void**)&xr,  g_xr);
    cudaGetSymbolAddress((void**)&wqkv, g_wqkv);
    cudaGetSymbolAddress((void**)&wor, g_wor);

    cudaFuncSetAttribute(attn_kernel, cudaFuncAttributeMaxDynamicSharedMemorySize,
                         ATT_SMEM_BYTES);
    cudaFuncSetAttribute(gemm_tf32, cudaFuncAttributeMaxDynamicSharedMemorySize,
                         GEMM_SMEM_BYTES);

    // fused tf32 pre-rounding, 4 float4 per thread
    {
        size_t nthreads = ROUND_TOTAL4 / 4;
        round_all_kernel<<<(unsigned)((nthreads + 255) / 256), 256>>>(x, Wq, Wk, Wv, Wo,
                                                                      xr, wqkv, wor);
    }

    // fused QKV projection: [8192 x 4096] = xr @ Wqkv^T
    gemm_tf32<<<dim3(QKVN / TBN, M_ / TBM), 256, GEMM_SMEM_BYTES>>>(xr, wqkv, qkv, M_, QKVN, C_);

    // RoPE on q and k, tf32-rounded outputs
    {
        int qpairs = M_ * NH_ * 64;
        int kpairs = M_ * NKV_ * 64;
        rope_kernel<<<(qpairs + 255) / 256, 256>>>(qkv, 0,  NH_,  qpairs);
        rope_kernel<<<(kpairs + 255) / 256, 256>>>(qkv, C_, NKV_, kpairs);
    }

    // V transpose -> (b,kvh,hd,t), tf32-rounded
    vtrans_kernel<<<dim3(T_ / 32, HD_ / 32, B_ * NKV_), dim3(32, 8)>>>(qkv, vt);

    // attention (tensor cores, 128-row Q tiles, 512 threads)
    attn_kernel<<<dim3(T_ / ABM, NH_, B_), ATT_THREADS, ATT_SMEM_BYTES>>>(qkv, vt, o);

    // output projection
    gemm_tf32<<<dim3(C_ / TBN, M_ / TBM), 256, GEMM_SMEM_BYTES>>>(o, wor, y, M_, C_, C_);
}

// round 12
// speedup vs baseline: 1.7069x; 1.7069x over previous
#include <cuda_runtime.h>
#include <cuda_fp16.h>
#include <math.h>
#include <stdint.h>

// Problem constants
#define B_    4
#define T_    2048
#define C_    2048
#define NH_   16
#define NKV_  8
#define HD_   128
#define M_    (B_*T_)          // 8192
#define KVD_  (NKV_*HD_)       // 1024
#define QKVN  (C_ + 2*KVD_)    // 4096

// ---------------- scratch ----------------------------------------------------
__device__ float  g_qkv[(size_t)M_ * QKVN];          // fused QKV out (fp32)
__device__ __half g_xh[(size_t)M_ * C_];             // x in fp16
__device__ __half g_wqkvh[(size_t)QKVN * C_];        // Wq|Wk|Wv fp16
__device__ __half g_worh[(size_t)C_ * C_];           // Wo fp16
__device__ __half g_qh[(size_t)M_ * C_];             // Q post-rope fp16
__device__ __half g_kh[(size_t)M_ * KVD_];           // K post-rope fp16
__device__ __half g_vth[(size_t)B_ * NKV_ * HD_ * T_]; // V transposed fp16
__device__ __half g_oh[(size_t)M_ * C_];             // attention out fp16

// ---------------- helpers ----------------------------------------------------
__device__ __forceinline__ void cp_async16(void* smem, const void* gmem) {
    uint32_t sa = (uint32_t)__cvta_generic_to_shared(smem);
    asm volatile("cp.async.cg.shared.global [%0], [%1], 16;\n" :: "r"(sa), "l"(gmem));
}
#define CP_COMMIT() asm volatile("cp.async.commit_group;\n" ::: "memory")
#define CP_WAIT(n)  asm volatile("cp.async.wait_group %0;\n" :: "n"(n) : "memory")

#define MMA_F16(d, a, b) \
    asm volatile("mma.sync.aligned.m16n8k16.row.col.f32.f16.f16.f32 " \
                 "{%0,%1,%2,%3}, {%4,%5,%6,%7}, {%8,%9}, {%0,%1,%2,%3};" \
                 : "+f"(d[0]), "+f"(d[1]), "+f"(d[2]), "+f"(d[3]) \
                 : "r"(a[0]), "r"(a[1]), "r"(a[2]), "r"(a[3]), "r"(b[0]), "r"(b[1]))

__device__ __forceinline__ void ldsm4(uint32_t* r, const void* p) {
    uint32_t a = (uint32_t)__cvta_generic_to_shared(p);
    asm volatile("ldmatrix.sync.aligned.m8n8.x4.shared.b16 {%0,%1,%2,%3}, [%4];"
                 : "=r"(r[0]), "=r"(r[1]), "=r"(r[2]), "=r"(r[3]) : "r"(a));
}

// ---------------- fused fp16 conversion pass (MLP=4) --------------------------
__global__ void round_all_kernel(const float* __restrict__ x,  const float* __restrict__ Wq,
                                 const float* __restrict__ Wk, const float* __restrict__ Wv,
                                 const float* __restrict__ Wo) {
    const size_t NX = (size_t)M_ * C_ / 4;
    const size_t NQ = (size_t)C_ * C_ / 4;
    const size_t NK = (size_t)KVD_ * C_ / 4;
    size_t j = ((size_t)blockIdx.x * blockDim.x + threadIdx.x) * 4;   // float4 idx
    const float4* src; __half* dst; size_t off;
    if (j < NX)                    { src = (const float4*)x;  dst = g_xh;    off = j; }
    else if (j < NX + NQ)          { src = (const float4*)Wq; dst = g_wqkvh; off = j - NX; }
    else if (j < NX + NQ + NK)     { src = (const float4*)Wk; dst = g_wqkvh + (size_t)C_ * C_; off = j - NX - NQ; }
    else if (j < NX + NQ + 2*NK)   { src = (const float4*)Wv; dst = g_wqkvh + (size_t)(C_ + KVD_) * C_; off = j - NX - NQ - NK; }
    else if (j < NX + 2*NQ + 2*NK) { src = (const float4*)Wo; dst = g_worh;  off = j - NX - NQ - 2*NK; }
    else return;
#pragma unroll
    for (int i = 0; i < 4; i++) {
        float4 v = src[off + i];
        *(__half2*)(dst + (off + i) * 4)     = __floats2half2_rn(v.x, v.y);
        *(__half2*)(dst + (off + i) * 4 + 2) = __floats2half2_rn(v.z, v.w);
    }
}
#define ROUND_TOTAL4 ((size_t)M_*C_/4 + 2*((size_t)C_*C_/4) + 2*((size_t)KVD_*C_/4))

// ---------------- fp16 tensor-core GEMM: C[M,N] = A[M,K] * B[N,K]^T ----------
#define HBM 128
#define HBN 128
#define HBK 32
#define HSTR 40   // halves; 80B row stride -> conflict-free ldmatrix
#define GEMMH_SMEM_BYTES (2 * (HBM * HSTR + HBN * HSTR) * 2)   // 40960

__global__ void __launch_bounds__(256, 2) gemm_h(const __half* __restrict__ A,
                                                 const __half* __restrict__ Bm,
                                                 float* __restrict__ Cm,
                                                 int M, int N, int K) {
    extern __shared__ __half hs[];
    __half* As = hs;                       // [2][128*40]
    __half* Bs = hs + 2 * HBM * HSTR;

    const int tid = threadIdx.x;
    const int wid = tid >> 5;
    const int lane = tid & 31;
    const int warp_m = wid >> 2;           // 0..1
    const int warp_n = wid & 3;            // 0..3
    const int g = lane >> 2;
    const int t = lane & 3;

    const int rowA  = lane & 15;
    const int koffA = (lane >> 4) * 8;     // halves (16B)
    const int rowB  = (lane & 7) + ((lane >> 4) << 3);
    const int koffB = ((lane >> 3) & 1) * 8;

    const __half* Ag = A + (size_t)blockIdx.y * HBM * K;
    const __half* Bg = Bm + (size_t)blockIdx.x * HBN * K;

    float c[4][4][4];
#pragma unroll
    for (int mt = 0; mt < 4; mt++)
#pragma unroll
        for (int nt = 0; nt < 4; nt++)
#pragma unroll
            for (int r = 0; r < 4; r++) c[mt][nt][r] = 0.f;

    auto load_tile = [&](int it, int buf) {
        int k0 = it * HBK;
        __half* as = As + buf * HBM * HSTR;
        __half* bs = Bs + buf * HBN * HSTR;
#pragma unroll
        for (int i = 0; i < 2; i++) {
            int idx = i * 256 + tid;
            int r = idx >> 2, cc = idx & 3;         // 4 x 16B chunks per row
            cp_async16(as + r * HSTR + cc * 8, Ag + (size_t)r * K + k0 + cc * 8);
            cp_async16(bs + r * HSTR + cc * 8, Bg + (size_t)r * K + k0 + cc * 8);
        }
    };

    const int NIT = K / HBK;
    load_tile(0, 0);
    CP_COMMIT();

    for (int it = 0; it < NIT; ++it) {
        int cur = it & 1;
        if (it + 1 < NIT) {
            load_tile(it + 1, cur ^ 1);
            CP_COMMIT();
            CP_WAIT(1);
        } else {
            CP_WAIT(0);
        }
        __syncthreads();

        const __half* as = As + cur * HBM * HSTR;
        const __half* bs = Bs + cur * HBN * HSTR;

#pragma unroll
        for (int kk = 0; kk < HBK; kk += 16) {
            uint32_t af[4][4], bf4[2][4];
#pragma unroll
            for (int mt = 0; mt < 4; mt++)
                ldsm4(af[mt], as + (warp_m * 64 + mt * 16 + rowA) * HSTR + kk + koffA);
#pragma unroll
            for (int np = 0; np < 2; np++)
                ldsm4(bf4[np], bs + (warp_n * 32 + np * 16 + rowB) * HSTR + kk + koffB);
#pragma unroll
            for (int mt = 0; mt < 4; mt++)
#pragma unroll
                for (int nt = 0; nt < 4; nt++)
                    MMA_F16(c[mt][nt], af[mt], (&bf4[nt >> 1][(nt & 1) * 2]));
        }
        __syncthreads();
    }

    const int row_base = blockIdx.y * HBM + warp_m * 64;
    const int col_base = blockIdx.x * HBN + warp_n * 32;
#pragma unroll
    for (int mt = 0; mt < 4; mt++) {
#pragma unroll
        for (int nt = 0; nt < 4; nt++) {
            int row = row_base + mt * 16 + g;
            int col = col_base + nt * 8 + 2 * t;
            *(float2*)(Cm + (size_t)row * N + col)       = make_float2(c[mt][nt][0], c[mt][nt][1]);
            *(float2*)(Cm + (size_t)(row + 8) * N + col) = make_float2(c[mt][nt][2], c[mt][nt][3]);
        }
    }
}

// ---------------- RoPE: read fp32 qkv, write fp16 q/k ------------------------
__global__ void rope_h_kernel(const float* __restrict__ qkv, __half* __restrict__ out,
                              int col_off, int nheads, int total_pairs) {
    int idx = blockIdx.x * blockDim.x + threadIdx.x;
    if (idx >= total_pairs) return;
    int d   = idx & 63;
    int tmp = idx >> 6;
    int h   = tmp % nheads;
    int bt  = tmp / nheads;
    int t   = bt & (T_ - 1);

    const float* base = qkv + (size_t)bt * QKVN + col_off + h * HD_;
    float x1 = base[d];
    float x2 = base[d + 64];

    int i1 = d >> 1;
    const float L2C = 0.20762050593046f; // log2(10000)/64
    float inv1 = exp2f(-(float)i1 * L2C);
    float inv2 = exp2f(-(float)(i1 + 32) * L2C);
    float a1 = (float)t * inv1;
    float a2 = (float)t * inv2;
    float s1, c1, s2, c2;
    sincosf(a1, &s1, &c1);
    sincosf(a2, &s2, &c2);

    __half* ob = out + ((size_t)bt * nheads + h) * HD_;
    ob[d]      = __float2half_rn(x1 * c1 - x2 * s1);
    ob[d + 64] = __float2half_rn(x2 * c2 + x1 * s2);
}

// ---------------- V transpose: fp32 qkv V cols -> fp16 (b,kvh,hd,t) ----------
__global__ void vtrans_h_kernel(const float* __restrict__ qkv, __half* __restrict__ Vt) {
    __shared__ float tile[32][33];
    const int z = blockIdx.z;
    const int b = z / NKV_;
    const int kvh = z % NKV_;
    const int t0 = blockIdx.x * 32;
    const int h0 = blockIdx.y * 32;

#pragma unroll
    for (int i = 0; i < 4; i++) {
        int tt = t0 + threadIdx.y + i * 8;
        tile[threadIdx.y + i * 8][threadIdx.x] =
            qkv[(size_t)(b * T_ + tt) * QKVN + C_ + KVD_ + kvh * HD_ + h0 + threadIdx.x];
    }
    __syncthreads();
#pragma unroll
    for (int i = 0; i < 4; i++) {
        int hd = h0 + threadIdx.y + i * 8;
        int tt = t0 + threadIdx.x;
        Vt[((size_t)(b * NKV_ + kvh) * HD_ + hd) * T_ + tt] =
            __float2half_rn(tile[threadIdx.x][threadIdx.y + i * 8]);
    }
}

// ---------------- Flash attention (fp16 TC, 128x64 tiles, occ 2) -------------
#define ABM 128
#define ABN 64
#define AH_QST 136        // halves; 272B row stride, conflict-free
#define AH_VST 72         // 144B
#define AH_PST 72

// halves: Q 128*136 + K 2*64*136 + V 128*72 + P 128*72; floats: 3*128 stats
#define ATTH_SMEM_BYTES ((128*AH_QST + 2*64*AH_QST + 128*AH_VST + 128*AH_PST) * 2 + 3 * 128 * 4) // 108032

__global__ void __launch_bounds__(256, 2) attn_h_kernel(const __half* __restrict__ Qh,
                                                        const __half* __restrict__ Kh,
                                                        const __half* __restrict__ Vth,
                                                        __half* __restrict__ Oh) {
    const int qt  = (int)gridDim.x - 1 - (int)blockIdx.x; // big tiles first
    const int h   = blockIdx.y;
    const int b   = blockIdx.z;
    const int kvh = h >> 1;

    extern __shared__ __half sh[];
    __half* Qs = sh;                           // [128][136]
    __half* Ks = Qs + 128 * AH_QST;            // [2][64][136]
    __half* Vs = Ks + 2 * 64 * AH_QST;         // [128][72]  (hd x seq)
    __half* Ps = Vs + 128 * AH_VST;            // [128][72]  (m x seq)
    float*  Ms = (float*)(Ps + 128 * AH_PST);
    float*  Ls = Ms + 128;
    float*  Al = Ls + 128;

    const int tid  = threadIdx.x;
    const int wid  = tid >> 5;                 // 0..7
    const int lane = tid & 31;
    const int g = lane >> 2;
    const int t = lane & 3;
    // QK phase: warp owns rows [16*wid, 16*wid+16), all 64 cols
    const int qrow0 = wid * 16;
    // PV phase: 4x2 warp grid
    const int warp_m = wid & 3;
    const int warp_n = wid >> 2;               // 0..1
    const int rband = warp_m * 32;
    const int ocol0 = warp_n * 64;

    const int rowA  = lane & 15;
    const int koffA = (lane >> 4) * 8;         // halves
    const int rowB  = (lane & 7) + ((lane >> 4) << 3);
    const int koffB = ((lane >> 3) & 1) * 8;

    const int q0 = qt * ABM;
    const int jtmax = 2 * qt + 1;
    const __half* vtb = Vth + (size_t)(b * NKV_ + kvh) * HD_ * T_;
    const __half* qb  = Qh + ((size_t)(b * T_ + q0) * NH_ + h) * HD_;
    const __half* kb  = Kh + ((size_t)(b * T_) * NKV_ + kvh) * HD_;

    // preload Q tile (plain 16B loads)
#pragma unroll
    for (int i = 0; i < 8; i++) {
        int v = i * 256 + tid;
        int r = v >> 4, c = v & 15;
        *(uint4*)(Qs + r * AH_QST + c * 8) = *(const uint4*)(qb + (size_t)r * (NH_ * HD_) + c * 8);
    }
    if (tid < 128) { Ms[tid] = -1e30f; Ls[tid] = 0.f; }

    auto load_k = [&](int jt, int buf) {
        const int j0 = jt * ABN;
        __half* ks = Ks + buf * 64 * AH_QST;
#pragma unroll
        for (int i = 0; i < 4; i++) {
            int v = i * 256 + tid;
            int r = v >> 4, c = v & 15;
            cp_async16(ks + r * AH_QST + c * 8, kb + (size_t)(j0 + r) * (NKV_ * HD_) + c * 8);
        }
    };
    auto load_v = [&](int jt) {
        const int j0 = jt * ABN;
#pragma unroll
        for (int i = 0; i < 4; i++) {
            int v = i * 256 + tid;
            int r = v >> 3, c = v & 7;
            cp_async16(Vs + r * AH_VST + c * 8, vtb + (size_t)r * T_ + j0 + c * 8);
        }
    };

    float o[2][8][4];
#pragma unroll
    for (int mt = 0; mt < 2; mt++)
#pragma unroll
        for (int nt = 0; nt < 8; nt++)
#pragma unroll
            for (int r = 0; r < 4; r++) o[mt][nt][r] = 0.f;

    load_k(0, 0);
    CP_COMMIT();
    __syncthreads();

    const float scale = 0.08838834764831845f; // 1/sqrt(128)

    for (int jt = 0; jt <= jtmax; jt++) {
        const int cur = jt & 1;
        load_v(jt);
        CP_COMMIT();
        if (jt < jtmax) {
            load_k(jt + 1, cur ^ 1);
            CP_COMMIT();
            CP_WAIT(2);        // K(jt) done; V(jt), K(jt+1) in flight
        } else {
            CP_WAIT(1);
        }
        __syncthreads();

        // ---- S = Q K^T : warp = 16 rows x 64 cols, scores in registers ----
        const __half* ksf = Ks + cur * 64 * AH_QST;
        float s[8][4];
#pragma unroll
        for (int nt = 0; nt < 8; nt++)
#pragma unroll
            for (int r = 0; r < 4; r++) s[nt][r] = 0.f;

#pragma unroll
        for (int kk = 0; kk < HD_; kk += 16) {
            uint32_t af[4], bf4[4][4];
            ldsm4(af, Qs + (qrow0 + rowA) * AH_QST + kk + koffA);
#pragma unroll
            for (int np = 0; np < 4; np++)
                ldsm4(bf4[np], ksf + (np * 16 + rowB) * AH_QST + kk + koffB);
#pragma unroll
            for (int nt = 0; nt < 8; nt++)
                MMA_F16(s[nt], af, (&bf4[nt >> 1][(nt & 1) * 2]));
        }

        // ---- scale + mask + in-register softmax ----
        const bool diag = (jt >= 2 * qt);
        const int rl = qrow0 + g, rh = rl + 8;
        float mxlo = -1e30f, mxhi = -1e30f;
#pragma unroll
        for (int nt = 0; nt < 8; nt++) {
            int gc0 = jt * ABN + nt * 8 + 2 * t;
            s[nt][0] *= scale; s[nt][1] *= scale;
            s[nt][2] *= scale; s[nt][3] *= scale;
            if (diag) {
                if (gc0     > q0 + rl) s[nt][0] = -1e30f;
                if (gc0 + 1 > q0 + rl) s[nt][1] = -1e30f;
                if (gc0     > q0 + rh) s[nt][2] = -1e30f;
                if (gc0 + 1 > q0 + rh) s[nt][3] = -1e30f;
            }
            mxlo = fmaxf(mxlo, fmaxf(s[nt][0], s[nt][1]));
            mxhi = fmaxf(mxhi, fmaxf(s[nt][2], s[nt][3]));
        }
        mxlo = fmaxf(mxlo, __shfl_xor_sync(0xffffffffu, mxlo, 1));
        mxlo = fmaxf(mxlo, __shfl_xor_sync(0xffffffffu, mxlo, 2));
        mxhi = fmaxf(mxhi, __shfl_xor_sync(0xffffffffu, mxhi, 1));
        mxhi = fmaxf(mxhi, __shfl_xor_sync(0xffffffffu, mxhi, 2));
        float mplo = Ms[rl], mphi = Ms[rh];
        mxlo = fmaxf(mxlo, mplo);
        mxhi = fmaxf(mxhi, mphi);

        float sumlo = 0.f, sumhi = 0.f;
#pragma unroll
        for (int nt = 0; nt < 8; nt++) {
            int c0 = nt * 8 + 2 * t;
            __half h0 = __float2half_rn(__expf(s[nt][0] - mxlo));
            __half h1 = __float2half_rn(__expf(s[nt][1] - mxlo));
            __half h2 = __float2half_rn(__expf(s[nt][2] - mxhi));
            __half h3 = __float2half_rn(__expf(s[nt][3] - mxhi));
            sumlo += __half2float(h0) + __half2float(h1);
            sumhi += __half2float(h2) + __half2float(h3);
            *(__half2*)(Ps + rl * AH_PST + c0) = __halves2half2(h0, h1);
            *(__half2*)(Ps + rh * AH_PST + c0) = __halves2half2(h2, h3);
        }
        sumlo += __shfl_xor_sync(0xffffffffu, sumlo, 1);
        sumlo += __shfl_xor_sync(0xffffffffu, sumlo, 2);
        sumhi += __shfl_xor_sync(0xffffffffu, sumhi, 1);
        sumhi += __shfl_xor_sync(0xffffffffu, sumhi, 2);
        if (t == 0) {
            float alo = __expf(mplo - mxlo);
            float ahi = __expf(mphi - mxhi);
            Ms[rl] = mxlo; Ls[rl] = Ls[rl] * alo + sumlo; Al[rl] = alo;
            Ms[rh] = mxhi; Ls[rh] = Ls[rh] * ahi + sumhi; Al[rh] = ahi;
        }
        if (jt < jtmax) { CP_WAIT(1); } else { CP_WAIT(0); }   // V(jt) complete
        __syncthreads();

        // ---- O = alpha*O + P @ V : warp = 32 rows x 64 hd-cols ----
        {
#pragma unroll
            for (int mt = 0; mt < 2; mt++) {
                float al_lo = Al[rband + mt * 16 + g];
                float al_hi = Al[rband + mt * 16 + 8 + g];
#pragma unroll
                for (int nt = 0; nt < 8; nt++) {
                    o[mt][nt][0] *= al_lo; o[mt][nt][1] *= al_lo;
                    o[mt][nt][2] *= al_hi; o[mt][nt][3] *= al_hi;
                }
            }
#pragma unroll
            for (int kk = 0; kk < ABN; kk += 16) {
                uint32_t af[2][4], bf4[4][4];
#pragma unroll
                for (int mt = 0; mt < 2; mt++)
                    ldsm4(af[mt], Ps + (rband + mt * 16 + rowA) * AH_PST + kk + koffA);
#pragma unroll
                for (int np = 0; np < 4; np++)
                    ldsm4(bf4[np], Vs + (ocol0 + np * 16 + rowB) * AH_VST + kk + koffB);
#pragma unroll
                for (int mt = 0; mt < 2; mt++)
#pragma unroll
                    for (int nt = 0; nt < 8; nt++)
                        MMA_F16(o[mt][nt], af[mt], (&bf4[nt >> 1][(nt & 1) * 2]));
            }
        }
        __syncthreads();   // protect V/P rewrite next iter
    }

    // ---- epilogue: divide by l, write fp16 O ----
#pragma unroll
    for (int mt = 0; mt < 2; mt++) {
        int rlo = rband + mt * 16 + g, rhi = rlo + 8;
        float inv_lo = 1.f / Ls[rlo];
        float inv_hi = 1.f / Ls[rhi];
        __half* dlo = Oh + ((size_t)(b * T_ + q0 + rlo) * NH_ + h) * HD_;
        __half* dhi = Oh + ((size_t)(b * T_ + q0 + rhi) * NH_ + h) * HD_;
#pragma unroll
        for (int nt = 0; nt < 8; nt++) {
            int col = ocol0 + nt * 8 + 2 * t;
            *(__half2*)(dlo + col) = __floats2half2_rn(o[mt][nt][0] * inv_lo,
                                                       o[mt][nt][1] * inv_lo);
            *(__half2*)(dhi + col) = __floats2half2_rn(o[mt][nt][2] * inv_hi,
                                                       o[mt][nt][3] * inv_hi);
        }
    }
}

// ---------------- launch ------------------------------------------------------
extern "C" void kernel_launch(void* const* d_in, const int* in_sizes, int n_in,
                              void* d_out, int out_size) {
    const float* x  = (const float*)d_in[0];
    const float* Wq = (const float*)d_in[1];
    const float* Wk = (const float*)d_in[2];
    const float* Wv = (const float*)d_in[3];
    const float* Wo = (const float*)d_in[4];
    float* y = (float*)d_out;

    float*  qkv;  __half *xh, *wqkvh, *worh, *qh, *kh, *vth, *oh;
    cudaGetSymbolAddress((void**)&qkv,   g_qkv);
    cudaGetSymbolAddress((void**)&xh,    g_xh);
    cudaGetSymbolAddress((void**)&wqkvh, g_wqkvh);
    cudaGetSymbolAddress((void**)&worh,  g_worh);
    cudaGetSymbolAddress((void**)&qh,    g_qh);
    cudaGetSymbolAddress((void**)&kh,    g_kh);
    cudaGetSymbolAddress((void**)&vth,   g_vth);
    cudaGetSymbolAddress((void**)&oh,    g_oh);

    cudaFuncSetAttribute(attn_h_kernel, cudaFuncAttributeMaxDynamicSharedMemorySize,
                         ATTH_SMEM_BYTES);
    cudaFuncSetAttribute(gemm_h, cudaFuncAttributeMaxDynamicSharedMemorySize,
                         GEMMH_SMEM_BYTES);

    // fp16 conversion of all GEMM operands
    {
        size_t nthreads = ROUND_TOTAL4 / 4;
        round_all_kernel<<<(unsigned)((nthreads + 255) / 256), 256>>>(x, Wq, Wk, Wv, Wo);
    }

    // fused QKV projection (fp16 MMA, fp32 out): [8192 x 4096]
    gemm_h<<<dim3(QKVN / HBN, M_ / HBM), 256, GEMMH_SMEM_BYTES>>>(xh, wqkvh, qkv, M_, QKVN, C_);

    // RoPE -> fp16 q/k
    {
        int qpairs = M_ * NH_ * 64;
        int kpairs = M_ * NKV_ * 64;
        rope_h_kernel<<<(qpairs + 255) / 256, 256>>>(qkv, qh, 0,  NH_,  qpairs);
        rope_h_kernel<<<(kpairs + 255) / 256, 256>>>(qkv, kh, C_, NKV_, kpairs);
    }

    // V transpose -> fp16 (b,kvh,hd,t)
    vtrans_h_kernel<<<dim3(T_ / 32, HD_ / 32, B_ * NKV_), dim3(32, 8)>>>(qkv, vth);

    // attention (fp16 tensor cores, 128-row Q tiles, occupancy 2)
    attn_h_kernel<<<dim3(T_ / ABM, NH_, B_), 256, ATTH_SMEM_BYTES>>>(qh, kh, vth, oh);

    // output projection (fp16 MMA, fp32 out)
    gemm_h<<<dim3(C_ / HBN, M_ / HBM), 256, GEMMH_SMEM_BYTES>>>(oh, worh, y, M_, C_, C_);
}

// round 13
// speedup vs baseline: 1.7847x; 1.0456x over previous
#include <cuda_runtime.h>
#include <cuda_fp16.h>
#include <math.h>
#include <stdint.h>

// Problem constants
#define B_    4
#define T_    2048
#define C_    2048
#define NH_   16
#define NKV_  8
#define HD_   128
#define M_    (B_*T_)          // 8192
#define KVD_  (NKV_*HD_)       // 1024
#define QKVN  (C_ + 2*KVD_)    // 4096

// ---------------- scratch ----------------------------------------------------
__device__ __half g_xh[(size_t)M_ * C_];               // x fp16
__device__ __half g_wqkvh[(size_t)QKVN * C_];          // Wq|Wk|Wv fp16
__device__ __half g_worh[(size_t)C_ * C_];             // Wo fp16
__device__ __half g_qkvh[(size_t)M_ * QKVN];           // fused QKV out fp16 (rope in place)
__device__ __half g_vth[(size_t)B_ * NKV_ * HD_ * T_]; // V transposed fp16
__device__ __half g_oh[(size_t)M_ * C_];               // attention out fp16

// ---------------- helpers ----------------------------------------------------
__device__ __forceinline__ void cp_async16(void* smem, const void* gmem) {
    uint32_t sa = (uint32_t)__cvta_generic_to_shared(smem);
    asm volatile("cp.async.cg.shared.global [%0], [%1], 16;\n" :: "r"(sa), "l"(gmem));
}
#define CP_COMMIT() asm volatile("cp.async.commit_group;\n" ::: "memory")
#define CP_WAIT(n)  asm volatile("cp.async.wait_group %0;\n" :: "n"(n) : "memory")

#define MMA_F16(d, a, b) \
    asm volatile("mma.sync.aligned.m16n8k16.row.col.f32.f16.f16.f32 " \
                 "{%0,%1,%2,%3}, {%4,%5,%6,%7}, {%8,%9}, {%0,%1,%2,%3};" \
                 : "+f"(d[0]), "+f"(d[1]), "+f"(d[2]), "+f"(d[3]) \
                 : "r"(a[0]), "r"(a[1]), "r"(a[2]), "r"(a[3]), "r"(b[0]), "r"(b[1]))

__device__ __forceinline__ void ldsm4(uint32_t* r, const void* p) {
    uint32_t a = (uint32_t)__cvta_generic_to_shared(p);
    asm volatile("ldmatrix.sync.aligned.m8n8.x4.shared.b16 {%0,%1,%2,%3}, [%4];"
                 : "=r"(r[0]), "=r"(r[1]), "=r"(r[2]), "=r"(r[3]) : "r"(a));
}

__device__ __forceinline__ void store2(float* p, float a, float b) {
    *(float2*)p = make_float2(a, b);
}
__device__ __forceinline__ void store2(__half* p, float a, float b) {
    *(__half2*)p = __floats2half2_rn(a, b);
}

// ---------------- fused fp16 conversion pass (MLP=4) --------------------------
__global__ void round_all_kernel(const float* __restrict__ x,  const float* __restrict__ Wq,
                                 const float* __restrict__ Wk, const float* __restrict__ Wv,
                                 const float* __restrict__ Wo) {
    const size_t NX = (size_t)M_ * C_ / 4;
    const size_t NQ = (size_t)C_ * C_ / 4;
    const size_t NK = (size_t)KVD_ * C_ / 4;
    size_t j = ((size_t)blockIdx.x * blockDim.x + threadIdx.x) * 4;   // float4 idx
    const float4* src; __half* dst; size_t off;
    if (j < NX)                    { src = (const float4*)x;  dst = g_xh;    off = j; }
    else if (j < NX + NQ)          { src = (const float4*)Wq; dst = g_wqkvh; off = j - NX; }
    else if (j < NX + NQ + NK)     { src = (const float4*)Wk; dst = g_wqkvh + (size_t)C_ * C_; off = j - NX - NQ; }
    else if (j < NX + NQ + 2*NK)   { src = (const float4*)Wv; dst = g_wqkvh + (size_t)(C_ + KVD_) * C_; off = j - NX - NQ - NK; }
    else if (j < NX + 2*NQ + 2*NK) { src = (const float4*)Wo; dst = g_worh;  off = j - NX - NQ - 2*NK; }
    else return;
#pragma unroll
    for (int i = 0; i < 4; i++) {
        float4 v = src[off + i];
        *(__half2*)(dst + (off + i) * 4)     = __floats2half2_rn(v.x, v.y);
        *(__half2*)(dst + (off + i) * 4 + 2) = __floats2half2_rn(v.z, v.w);
    }
}
#define ROUND_TOTAL4 ((size_t)M_*C_/4 + 2*((size_t)C_*C_/4) + 2*((size_t)KVD_*C_/4))

// ---------------- fp16 tensor-core GEMM: C[M,N] = A[M,K] * B[N,K]^T ----------
#define HBM 128
#define HBN 128
#define HBK 32
#define HSTR 40   // halves; 80B row stride -> conflict-free ldmatrix
#define GEMMH_SMEM_BYTES (2 * (HBM * HSTR + HBN * HSTR) * 2)   // 40960

template <typename OT>
__global__ void __launch_bounds__(256, 2) gemm_h(const __half* __restrict__ A,
                                                 const __half* __restrict__ Bm,
                                                 OT* __restrict__ Cm,
                                                 int M, int N, int K) {
    extern __shared__ __half hs[];
    __half* As = hs;
    __half* Bs = hs + 2 * HBM * HSTR;

    const int tid = threadIdx.x;
    const int wid = tid >> 5;
    const int lane = tid & 31;
    const int warp_m = wid >> 2;
    const int warp_n = wid & 3;
    const int g = lane >> 2;
    const int t = lane & 3;

    const int rowA  = lane & 15;
    const int koffA = (lane >> 4) * 8;
    const int rowB  = (lane & 7) + ((lane >> 4) << 3);
    const int koffB = ((lane >> 3) & 1) * 8;

    const __half* Ag = A + (size_t)blockIdx.y * HBM * K;
    const __half* Bg = Bm + (size_t)blockIdx.x * HBN * K;

    float c[4][4][4];
#pragma unroll
    for (int mt = 0; mt < 4; mt++)
#pragma unroll
        for (int nt = 0; nt < 4; nt++)
#pragma unroll
            for (int r = 0; r < 4; r++) c[mt][nt][r] = 0.f;

    auto load_tile = [&](int it, int buf) {
        int k0 = it * HBK;
        __half* as = As + buf * HBM * HSTR;
        __half* bs = Bs + buf * HBN * HSTR;
#pragma unroll
        for (int i = 0; i < 2; i++) {
            int idx = i * 256 + tid;
            int r = idx >> 2, cc = idx & 3;
            cp_async16(as + r * HSTR + cc * 8, Ag + (size_t)r * K + k0 + cc * 8);
            cp_async16(bs + r * HSTR + cc * 8, Bg + (size_t)r * K + k0 + cc * 8);
        }
    };

    const int NIT = K / HBK;
    load_tile(0, 0);
    CP_COMMIT();

    for (int it = 0; it < NIT; ++it) {
        int cur = it & 1;
        if (it + 1 < NIT) {
            load_tile(it + 1, cur ^ 1);
            CP_COMMIT();
            CP_WAIT(1);
        } else {
            CP_WAIT(0);
        }
        __syncthreads();

        const __half* as = As + cur * HBM * HSTR;
        const __half* bs = Bs + cur * HBN * HSTR;

#pragma unroll
        for (int kk = 0; kk < HBK; kk += 16) {
            uint32_t af[4][4], bf4[2][4];
#pragma unroll
            for (int mt = 0; mt < 4; mt++)
                ldsm4(af[mt], as + (warp_m * 64 + mt * 16 + rowA) * HSTR + kk + koffA);
#pragma unroll
            for (int np = 0; np < 2; np++)
                ldsm4(bf4[np], bs + (warp_n * 32 + np * 16 + rowB) * HSTR + kk + koffB);
#pragma unroll
            for (int mt = 0; mt < 4; mt++)
#pragma unroll
                for (int nt = 0; nt < 4; nt++)
                    MMA_F16(c[mt][nt], af[mt], (&bf4[nt >> 1][(nt & 1) * 2]));
        }
        __syncthreads();
    }

    const int row_base = blockIdx.y * HBM + warp_m * 64;
    const int col_base = blockIdx.x * HBN + warp_n * 32;
#pragma unroll
    for (int mt = 0; mt < 4; mt++) {
#pragma unroll
        for (int nt = 0; nt < 4; nt++) {
            int row = row_base + mt * 16 + g;
            int col = col_base + nt * 8 + 2 * t;
            store2(Cm + (size_t)row * N + col,       c[mt][nt][0], c[mt][nt][1]);
            store2(Cm + (size_t)(row + 8) * N + col, c[mt][nt][2], c[mt][nt][3]);
        }
    }
}

// ---------------- RoPE in place on fp16 qkv (q + k fused, half2) -------------
// one thread = 2 adjacent pairs (d2, d2+1) + (d2+64, d2+65); shared sincos
__global__ void rope_h_kernel(__half* __restrict__ qkv, int total) {
    int idx = blockIdx.x * blockDim.x + threadIdx.x;
    if (idx >= total) return;
    int d2  = (idx & 31) * 2;          // 0,2,..,62
    int tmp = idx >> 5;
    int hh  = tmp % (NH_ + NKV_);      // 0..23 (q heads then k heads)
    int bt  = tmp / (NH_ + NKV_);
    int t   = bt & (T_ - 1);

    int col = (hh < NH_) ? hh * HD_ : C_ + (hh - NH_) * HD_;
    __half* base = qkv + (size_t)bt * QKVN + col;

    __half2 lo = *(__half2*)(base + d2);
    __half2 hi = *(__half2*)(base + d2 + 64);
    float x1a = __low2float(lo),  x1b = __high2float(lo);
    float x2a = __low2float(hi),  x2b = __high2float(hi);

    int i1 = d2 >> 1;
    const float L2C = 0.20762050593046f; // log2(10000)/64
    float inv1 = exp2f(-(float)i1 * L2C);
    float inv2 = exp2f(-(float)(i1 + 32) * L2C);
    float s1, c1, s2, c2;
    sincosf((float)t * inv1, &s1, &c1);
    sincosf((float)t * inv2, &s2, &c2);

    *(__half2*)(base + d2)      = __floats2half2_rn(x1a * c1 - x2a * s1, x1b * c1 - x2b * s1);
    *(__half2*)(base + d2 + 64) = __floats2half2_rn(x2a * c2 + x1a * s2, x2b * c2 + x1b * s2);
}

// ---------------- V transpose: fp16 qkv V cols -> fp16 (b,kvh,hd,t) ----------
__global__ void vtrans_h_kernel(const __half* __restrict__ qkv, __half* __restrict__ Vt) {
    __shared__ __half tile[32][34];
    const int z = blockIdx.z;
    const int b = z / NKV_;
    const int kvh = z % NKV_;
    const int t0 = blockIdx.x * 32;
    const int h0 = blockIdx.y * 32;

#pragma unroll
    for (int i = 0; i < 4; i++) {
        int tt = t0 + threadIdx.y + i * 8;
        tile[threadIdx.y + i * 8][threadIdx.x] =
            qkv[(size_t)(b * T_ + tt) * QKVN + C_ + KVD_ + kvh * HD_ + h0 + threadIdx.x];
    }
    __syncthreads();
#pragma unroll
    for (int i = 0; i < 4; i++) {
        int hd = h0 + threadIdx.y + i * 8;
        int tt = t0 + threadIdx.x;
        Vt[((size_t)(b * NKV_ + kvh) * HD_ + hd) * T_ + tt] = tile[threadIdx.x][threadIdx.y + i * 8];
    }
}

// ---------------- Flash attention: FA2-style, P in registers ------------------
// CTA = 128 q-rows, 8 warps x 16 rows; per iter 64 keys; K,V double-buffered.
#define ABM 128
#define ABN 64
#define AH_QST 136        // Q/K row stride (halves)
#define AH_VST 72         // V row stride (halves)
#define AQ_HALVES (128 * AH_QST)            // 17408
#define AK_HALVES (64 * AH_QST)             // 8704 per buf
#define AV_HALVES (128 * AH_VST)            // 9216 per buf
#define ATTH_SMEM_BYTES ((AQ_HALVES + 2 * AK_HALVES + 2 * AV_HALVES) * 2)  // 106496

__global__ void __launch_bounds__(256, 2) attn_h_kernel(const __half* __restrict__ QKVh,
                                                        const __half* __restrict__ Vth,
                                                        __half* __restrict__ Oh) {
    const int qt  = (int)gridDim.x - 1 - (int)blockIdx.x; // big tiles first
    const int h   = blockIdx.y;
    const int b   = blockIdx.z;
    const int kvh = h >> 1;

    extern __shared__ __half sh[];
    __half* Qs = sh;                       // [128][136]
    __half* Ks = Qs + AQ_HALVES;           // [2][64][136]
    __half* Vs = Ks + 2 * AK_HALVES;       // [2][128][72] (hd x seq)

    const int tid  = threadIdx.x;
    const int wid  = tid >> 5;             // 0..7, warp owns q-rows [16w,16w+16)
    const int lane = tid & 31;
    const int g = lane >> 2;
    const int t = lane & 3;
    const int qrow0 = wid * 16;

    const int rowA  = lane & 15;
    const int koffA = (lane >> 4) * 8;
    const int rowB  = (lane & 7) + ((lane >> 4) << 3);
    const int koffB = ((lane >> 3) & 1) * 8;

    const int q0 = qt * ABM;
    const int jtmax = 2 * qt + 1;
    const __half* vtb = Vth + (size_t)(b * NKV_ + kvh) * HD_ * T_;
    const __half* qb  = QKVh + (size_t)(b * T_ + q0) * QKVN + h * HD_;
    const __half* kb  = QKVh + (size_t)(b * T_) * QKVN + C_ + kvh * HD_;

    // preload Q (plain 16B loads)
#pragma unroll
    for (int i = 0; i < 8; i++) {
        int v = i * 256 + tid;
        int r = v >> 4, c = v & 15;
        *(uint4*)(Qs + r * AH_QST + c * 8) = *(const uint4*)(qb + (size_t)r * QKVN + c * 8);
    }

    auto load_kv = [&](int jt, int buf) {
        const int j0 = jt * ABN;
        __half* ks = Ks + buf * AK_HALVES;
        __half* vs = Vs + buf * AV_HALVES;
#pragma unroll
        for (int i = 0; i < 4; i++) {
            int v = i * 256 + tid;
            int r = v >> 4, c = v & 15;
            cp_async16(ks + r * AH_QST + c * 8, kb + (size_t)(j0 + r) * QKVN + c * 8);
        }
#pragma unroll
        for (int i = 0; i < 4; i++) {
            int v = i * 256 + tid;
            int r = v >> 3, c = v & 7;
            cp_async16(vs + r * AH_VST + c * 8, vtb + (size_t)r * T_ + j0 + c * 8);
        }
    };

    float o[16][4];
#pragma unroll
    for (int nt = 0; nt < 16; nt++)
#pragma unroll
        for (int r = 0; r < 4; r++) o[nt][r] = 0.f;
    float m_lo = -1e30f, m_hi = -1e30f, l_lo = 0.f, l_hi = 0.f;

    load_kv(0, 0);
    CP_COMMIT();

    const float scale = 0.08838834764831845f; // 1/sqrt(128)
    const int rl = qrow0 + g, rh = rl + 8;

    for (int jt = 0; jt <= jtmax; jt++) {
        const int cur = jt & 1;
        if (jt < jtmax) {
            load_kv(jt + 1, cur ^ 1);
            CP_COMMIT();
            CP_WAIT(1);          // K+V(jt) complete; (jt+1) in flight
        } else {
            CP_WAIT(0);
        }
        __syncthreads();          // K/V(jt) visible; Q visible (first iter)

        const __half* ksf = Ks + cur * AK_HALVES;
        const __half* vsf = Vs + cur * AV_HALVES;

        // ---- S = Q K^T : warp = 16 rows x 64 keys, scores in registers ----
        float s[8][4];
#pragma unroll
        for (int nt = 0; nt < 8; nt++)
#pragma unroll
            for (int r = 0; r < 4; r++) s[nt][r] = 0.f;

#pragma unroll
        for (int kk = 0; kk < HD_; kk += 16) {
            uint32_t af[4], bf[4][4];
            ldsm4(af, Qs + (qrow0 + rowA) * AH_QST + kk + koffA);
#pragma unroll
            for (int np = 0; np < 4; np++)
                ldsm4(bf[np], ksf + (np * 16 + rowB) * AH_QST + kk + koffB);
#pragma unroll
            for (int nt = 0; nt < 8; nt++)
                MMA_F16(s[nt], af, (&bf[nt >> 1][(nt & 1) * 2]));
        }

        // ---- scale + mask + softmax, all in registers ----
        const bool diag = (jt >= 2 * qt);
        float mxlo = -1e30f, mxhi = -1e30f;
#pragma unroll
        for (int nt = 0; nt < 8; nt++) {
            int gc0 = jt * ABN + nt * 8 + 2 * t;
            s[nt][0] *= scale; s[nt][1] *= scale;
            s[nt][2] *= scale; s[nt][3] *= scale;
            if (diag) {
                if (gc0     > q0 + rl) s[nt][0] = -1e30f;
                if (gc0 + 1 > q0 + rl) s[nt][1] = -1e30f;
                if (gc0     > q0 + rh) s[nt][2] = -1e30f;
                if (gc0 + 1 > q0 + rh) s[nt][3] = -1e30f;
            }
            mxlo = fmaxf(mxlo, fmaxf(s[nt][0], s[nt][1]));
            mxhi = fmaxf(mxhi, fmaxf(s[nt][2], s[nt][3]));
        }
        mxlo = fmaxf(mxlo, __shfl_xor_sync(0xffffffffu, mxlo, 1));
        mxlo = fmaxf(mxlo, __shfl_xor_sync(0xffffffffu, mxlo, 2));
        mxhi = fmaxf(mxhi, __shfl_xor_sync(0xffffffffu, mxhi, 1));
        mxhi = fmaxf(mxhi, __shfl_xor_sync(0xffffffffu, mxhi, 2));
        mxlo = fmaxf(mxlo, m_lo);
        mxhi = fmaxf(mxhi, m_hi);

        uint32_t ph[16];
        float sumlo = 0.f, sumhi = 0.f;
#pragma unroll
        for (int nt = 0; nt < 8; nt++) {
            float p0 = __expf(s[nt][0] - mxlo);
            float p1 = __expf(s[nt][1] - mxlo);
            float p2 = __expf(s[nt][2] - mxhi);
            float p3 = __expf(s[nt][3] - mxhi);
            __half2 plo = __floats2half2_rn(p0, p1);
            __half2 phi = __floats2half2_rn(p2, p3);
            sumlo += __low2float(plo) + __high2float(plo);
            sumhi += __low2float(phi) + __high2float(phi);
            ph[nt * 2]     = *(uint32_t*)&plo;   // A-frag (g,   k=nt*8+2t..)
            ph[nt * 2 + 1] = *(uint32_t*)&phi;   // A-frag (g+8, k=nt*8+2t..)
        }
        sumlo += __shfl_xor_sync(0xffffffffu, sumlo, 1);
        sumlo += __shfl_xor_sync(0xffffffffu, sumlo, 2);
        sumhi += __shfl_xor_sync(0xffffffffu, sumhi, 1);
        sumhi += __shfl_xor_sync(0xffffffffu, sumhi, 2);

        float alo = __expf(m_lo - mxlo);
        float ahi = __expf(m_hi - mxhi);
        m_lo = mxlo; l_lo = l_lo * alo + sumlo;
        m_hi = mxhi; l_hi = l_hi * ahi + sumhi;
#pragma unroll
        for (int nt = 0; nt < 16; nt++) {
            o[nt][0] *= alo; o[nt][1] *= alo;
            o[nt][2] *= ahi; o[nt][3] *= ahi;
        }

        // ---- O += P @ V : warp = 16 rows x 128 hd, P from registers ----
#pragma unroll
        for (int kk = 0; kk < ABN; kk += 16) {
            const int j = kk >> 4;
            uint32_t a[4] = { ph[4 * j], ph[4 * j + 1], ph[4 * j + 2], ph[4 * j + 3] };
            uint32_t bf[8][4];
#pragma unroll
            for (int np = 0; np < 8; np++)
                ldsm4(bf[np], vsf + (np * 16 + rowB) * AH_VST + kk + koffB);
#pragma unroll
            for (int nt = 0; nt < 16; nt++)
                MMA_F16(o[nt], a, (&bf[nt >> 1][(nt & 1) * 2]));
        }
        __syncthreads();          // all warps done reading cur buffers
    }

    // ---- epilogue ----
    float inv_lo = 1.f / l_lo;
    float inv_hi = 1.f / l_hi;
    __half* dlo = Oh + (size_t)(b * T_ + q0 + rl) * C_ + h * HD_;
    __half* dhi = Oh + (size_t)(b * T_ + q0 + rh) * C_ + h * HD_;
#pragma unroll
    for (int nt = 0; nt < 16; nt++) {
        int col = nt * 8 + 2 * t;
        *(__half2*)(dlo + col) = __floats2half2_rn(o[nt][0] * inv_lo, o[nt][1] * inv_lo);
        *(__half2*)(dhi + col) = __floats2half2_rn(o[nt][2] * inv_hi, o[nt][3] * inv_hi);
    }
}

// ---------------- launch ------------------------------------------------------
extern "C" void kernel_launch(void* const* d_in, const int* in_sizes, int n_in,
                              void* d_out, int out_size) {
    const float* x  = (const float*)d_in[0];
    const float* Wq = (const float*)d_in[1];
    const float* Wk = (const float*)d_in[2];
    const float* Wv = (const float*)d_in[3];
    const float* Wo = (const float*)d_in[4];
    float* y = (float*)d_out;

    __half *xh, *wqkvh, *worh, *qkvh, *vth, *oh;
    cudaGetSymbolAddress((void**)&xh,    g_xh);
    cudaGetSymbolAddress((void**)&wqkvh, g_wqkvh);
    cudaGetSymbolAddress((void**)&worh,  g_worh);
    cudaGetSymbolAddress((void**)&qkvh,  g_qkvh);
    cudaGetSymbolAddress((void**)&vth,   g_vth);
    cudaGetSymbolAddress((void**)&oh,    g_oh);

    cudaFuncSetAttribute(attn_h_kernel, cudaFuncAttributeMaxDynamicSharedMemorySize,
                         ATTH_SMEM_BYTES);
    cudaFuncSetAttribute(gemm_h<__half>, cudaFuncAttributeMaxDynamicSharedMemorySize,
                         GEMMH_SMEM_BYTES);
    cudaFuncSetAttribute(gemm_h<float>, cudaFuncAttributeMaxDynamicSharedMemorySize,
                         GEMMH_SMEM_BYTES);

    // fp16 conversion of all GEMM operands
    {
        size_t nthreads = ROUND_TOTAL4 / 4;
        round_all_kernel<<<(unsigned)((nthreads + 255) / 256), 256>>>(x, Wq, Wk, Wv, Wo);
    }

    // fused QKV projection, fp16 output: [8192 x 4096]
    gemm_h<__half><<<dim3(QKVN / HBN, M_ / HBM), 256, GEMMH_SMEM_BYTES>>>(xh, wqkvh, qkvh,
                                                                          M_, QKVN, C_);

    // RoPE in place on q+k columns of qkv (fused, half2)
    {
        int total = M_ * (NH_ + NKV_) * 32;
        rope_h_kernel<<<(total + 255) / 256, 256>>>(qkvh, total);
    }

    // V transpose -> fp16 (b,kvh,hd,t)
    vtrans_h_kernel<<<dim3(T_ / 32, HD_ / 32, B_ * NKV_), dim3(32, 8)>>>(qkvh, vth);

    // attention (fp16 TC, FA2 register-P, occupancy 2)
    attn_h_kernel<<<dim3(T_ / ABM, NH_, B_), 256, ATTH_SMEM_BYTES>>>(qkvh, vth, oh);

    // output projection, fp32 output
    gemm_h<float><<<dim3(C_ / HBN, M_ / HBM), 256, GEMMH_SMEM_BYTES>>>(oh, worh, y,
                                                                       M_, C_, C_);
}

// round 15
// speedup vs baseline: 1.8259x; 1.0231x over previous
#include <cuda_runtime.h>
#include <cuda_fp16.h>
#include <math.h>
#include <stdint.h>

// Problem constants
#define B_    4
#define T_    2048
#define C_    2048
#define NH_   16
#define NKV_  8
#define HD_   128
#define M_    (B_*T_)          // 8192
#define KVD_  (NKV_*HD_)       // 1024
#define QKVN  (C_ + 2*KVD_)    // 4096

// ---------------- scratch ----------------------------------------------------
__device__ __half g_wqkvh[(size_t)QKVN * C_];          // Wq|Wk|Wv fp16
__device__ __half g_worh[(size_t)C_ * C_];             // Wo fp16
__device__ __half g_qkvh[(size_t)M_ * QKVN];           // fused QKV out fp16 (q/k rope'd)
__device__ __half g_vth[(size_t)B_ * NKV_ * HD_ * T_]; // V transposed fp16
__device__ __half g_oh[(size_t)M_ * C_];               // attention out fp16
__device__ float4 g_ropetab[(size_t)T_ * 32];          // (c1,s1,c2,s2) per (t, i1)

// ---------------- helpers ----------------------------------------------------
__device__ __forceinline__ void cp_async16(void* smem, const void* gmem) {
    uint32_t sa = (uint32_t)__cvta_generic_to_shared(smem);
    asm volatile("cp.async.cg.shared.global [%0], [%1], 16;\n" :: "r"(sa), "l"(gmem));
}
#define CP_COMMIT() asm volatile("cp.async.commit_group;\n" ::: "memory")
#define CP_WAIT(n)  asm volatile("cp.async.wait_group %0;\n" :: "n"(n) : "memory")

#define MMA_F16(d, a, b) \
    asm volatile("mma.sync.aligned.m16n8k16.row.col.f32.f16.f16.f32 " \
                 "{%0,%1,%2,%3}, {%4,%5,%6,%7}, {%8,%9}, {%0,%1,%2,%3};" \
                 : "+f"(d[0]), "+f"(d[1]), "+f"(d[2]), "+f"(d[3]) \
                 : "r"(a[0]), "r"(a[1]), "r"(a[2]), "r"(a[3]), "r"(b[0]), "r"(b[1]))

__device__ __forceinline__ void ldsm4(uint32_t* r, const void* p) {
    uint32_t a = (uint32_t)__cvta_generic_to_shared(p);
    asm volatile("ldmatrix.sync.aligned.m8n8.x4.shared.b16 {%0,%1,%2,%3}, [%4];"
                 : "=r"(r[0]), "=r"(r[1]), "=r"(r[2]), "=r"(r[3]) : "r"(a));
}

__device__ __forceinline__ void store2(float* p, float a, float b) {
    *(float2*)p = make_float2(a, b);
}
__device__ __forceinline__ void store2(__half* p, float a, float b) {
    *(__half2*)p = __floats2half2_rn(a, b);
}

#define L2C_ 0.20762050593046f   // log2(10000)/64

// ---------------- rope table: (t, i1) -> cos/sin for freq i1 and i1+32 -------
__global__ void ropetab_kernel(float4* __restrict__ tab) {
    int idx = blockIdx.x * blockDim.x + threadIdx.x;
    if (idx >= T_ * 32) return;
    int t = idx >> 5, i = idx & 31;
    float inv1 = exp2f(-(float)i * L2C_);
    float inv2 = exp2f(-(float)(i + 32) * L2C_);
    float s1, c1, s2, c2;
    sincosf((float)t * inv1, &s1, &c1);
    sincosf((float)t * inv2, &s2, &c2);
    tab[idx] = make_float4(c1, s1, c2, s2);
}

// ---------------- weight fp16 conversion (MLP=4) ------------------------------
__global__ void round_w_kernel(const float* __restrict__ Wq, const float* __restrict__ Wk,
                               const float* __restrict__ Wv, const float* __restrict__ Wo) {
    const size_t NQ = (size_t)C_ * C_ / 4;
    const size_t NK = (size_t)KVD_ * C_ / 4;
    size_t j = ((size_t)blockIdx.x * blockDim.x + threadIdx.x) * 4;
    const float4* src; __half* dst; size_t off;
    if (j < NQ)                { src = (const float4*)Wq; dst = g_wqkvh; off = j; }
    else if (j < NQ + NK)      { src = (const float4*)Wk; dst = g_wqkvh + (size_t)C_ * C_; off = j - NQ; }
    else if (j < NQ + 2*NK)    { src = (const float4*)Wv; dst = g_wqkvh + (size_t)(C_ + KVD_) * C_; off = j - NQ - NK; }
    else if (j < 2*NQ + 2*NK)  { src = (const float4*)Wo; dst = g_worh;  off = j - NQ - 2*NK; }
    else return;
#pragma unroll
    for (int i = 0; i < 4; i++) {
        float4 v = src[off + i];
        *(__half2*)(dst + (off + i) * 4)     = __floats2half2_rn(v.x, v.y);
        *(__half2*)(dst + (off + i) * 4 + 2) = __floats2half2_rn(v.z, v.w);
    }
}
#define ROUNDW_TOTAL4 (2*((size_t)C_*C_/4) + 2*((size_t)KVD_*C_/4))

// ---------------- fp16 tensor-core GEMM: C[M,N] = A[M,K] * B[N,K]^T ----------
// AT=float: A converted fp32->fp16 in the loader (register-prefetched).
// DO_ROPE: blocks with blockIdx.x<24 (q/k heads) get rope applied in epilogue.
#define HBM 128
#define HBN 128
#define HBK 32
#define HSTR 40   // halves; 80B row stride -> conflict-free ldmatrix
#define GEMMH_SMEM_BYTES (2 * (HBM * HSTR + HBN * HSTR) * 2)   // 40960
#define RSTG 136  // rope stage stride (halves)

template <typename AT, typename OT, bool DO_ROPE>
__global__ void __launch_bounds__(256, 2) gemm_h(const AT* __restrict__ A,
                                                 const __half* __restrict__ Bm,
                                                 OT* __restrict__ Cm,
                                                 const float4* __restrict__ ropetab,
                                                 int M, int N, int K) {
    extern __shared__ __half hs[];
    __half* As = hs;
    __half* Bs = hs + 2 * HBM * HSTR;

    const int tid = threadIdx.x;
    const int wid = tid >> 5;
    const int lane = tid & 31;
    const int warp_m = wid >> 2;
    const int warp_n = wid & 3;
    const int g = lane >> 2;
    const int t = lane & 3;

    const int rowA  = lane & 15;
    const int koffA = (lane >> 4) * 8;
    const int rowB  = (lane & 7) + ((lane >> 4) << 3);
    const int koffB = ((lane >> 3) & 1) * 8;

    const AT* Ag = A + (size_t)blockIdx.y * HBM * K;
    const __half* Bg = Bm + (size_t)blockIdx.x * HBN * K;

    float c[4][4][4];
#pragma unroll
    for (int mt = 0; mt < 4; mt++)
#pragma unroll
        for (int nt = 0; nt < 4; nt++)
#pragma unroll
            for (int r = 0; r < 4; r++) c[mt][nt][r] = 0.f;

    auto load_B = [&](int it, int buf) {
        int k0 = it * HBK;
        __half* bs = Bs + buf * HBN * HSTR;
#pragma unroll
        for (int i = 0; i < 2; i++) {
            int idx = i * 256 + tid;
            int r = idx >> 2, cc = idx & 3;
            cp_async16(bs + r * HSTR + cc * 8, Bg + (size_t)r * K + k0 + cc * 8);
        }
    };
    auto load_A_async = [&](int it, int buf) {   // fp16 A path
        int k0 = it * HBK;
        __half* as = As + buf * HBM * HSTR;
#pragma unroll
        for (int i = 0; i < 2; i++) {
            int idx = i * 256 + tid;
            int r = idx >> 2, cc = idx & 3;
            cp_async16(as + r * HSTR + cc * 8, (const __half*)Ag + (size_t)r * K + k0 + cc * 8);
        }
    };

    float4 ra[4];
    auto ldg_A = [&](int it) {                  // fp32 A path: LDG into registers
        int k0 = it * HBK;
#pragma unroll
        for (int i = 0; i < 2; i++) {
            int idx = i * 256 + tid;
            int r = idx >> 2, cc = idx & 3;
            const float* p = (const float*)Ag + (size_t)r * K + k0 + cc * 8;
            ra[2 * i]     = *(const float4*)p;
            ra[2 * i + 1] = *(const float4*)(p + 4);
        }
    };
    auto sts_A = [&](int buf) {                 // convert + store
        __half* as = As + buf * HBM * HSTR;
#pragma unroll
        for (int i = 0; i < 2; i++) {
            int idx = i * 256 + tid;
            int r = idx >> 2, cc = idx & 3;
            __half2 h0 = __floats2half2_rn(ra[2*i].x,     ra[2*i].y);
            __half2 h1 = __floats2half2_rn(ra[2*i].z,     ra[2*i].w);
            __half2 h2 = __floats2half2_rn(ra[2*i+1].x,   ra[2*i+1].y);
            __half2 h3 = __floats2half2_rn(ra[2*i+1].z,   ra[2*i+1].w);
            uint4 u;
            u.x = *(uint32_t*)&h0; u.y = *(uint32_t*)&h1;
            u.z = *(uint32_t*)&h2; u.w = *(uint32_t*)&h3;
            *(uint4*)(as + r * HSTR + cc * 8) = u;
        }
    };

    constexpr bool A_F32 = (sizeof(AT) == 4);
    const int NIT = K / HBK;

    if constexpr (A_F32) {
        ldg_A(0);
        load_B(0, 0);
        CP_COMMIT();
        sts_A(0);
    } else {
        load_A_async(0, 0);
        load_B(0, 0);
        CP_COMMIT();
    }

    for (int it = 0; it < NIT; ++it) {
        int cur = it & 1;
        if (it + 1 < NIT) {
            if constexpr (A_F32) {
                ldg_A(it + 1);
                load_B(it + 1, cur ^ 1);
            } else {
                load_A_async(it + 1, cur ^ 1);
                load_B(it + 1, cur ^ 1);
            }
            CP_COMMIT();
            CP_WAIT(1);
        } else {
            CP_WAIT(0);
        }
        __syncthreads();

        const __half* as = As + cur * HBM * HSTR;
        const __half* bs = Bs + cur * HBN * HSTR;

#pragma unroll
        for (int kk = 0; kk < HBK; kk += 16) {
            uint32_t af[4][4], bf4[2][4];
#pragma unroll
            for (int mt = 0; mt < 4; mt++)
                ldsm4(af[mt], as + (warp_m * 64 + mt * 16 + rowA) * HSTR + kk + koffA);
#pragma unroll
            for (int np = 0; np < 2; np++)
                ldsm4(bf4[np], bs + (warp_n * 32 + np * 16 + rowB) * HSTR + kk + koffB);
#pragma unroll
            for (int mt = 0; mt < 4; mt++)
#pragma unroll
                for (int nt = 0; nt < 4; nt++)
                    MMA_F16(c[mt][nt], af[mt], (&bf4[nt >> 1][(nt & 1) * 2]));
        }

        if constexpr (A_F32) {
            if (it + 1 < NIT) sts_A(cur ^ 1);   // safe: writes nxt buf, visible after next sync
        }
        __syncthreads();
    }

    // ---------------- epilogue ----------------
    if (DO_ROPE && (int)blockIdx.x < 24) {
        // q/k head block: stage tile in smem, apply rope, store
        __half* Cs = hs;                        // reuse stage buffers (17408 <= 20480 halves)
#pragma unroll
        for (int mt = 0; mt < 4; mt++) {
#pragma unroll
            for (int nt = 0; nt < 4; nt++) {
                int row = warp_m * 64 + mt * 16 + g;
                int col = warp_n * 32 + nt * 8 + 2 * t;
                *(__half2*)(Cs + row * RSTG + col)       = __floats2half2_rn(c[mt][nt][0], c[mt][nt][1]);
                *(__half2*)(Cs + (row + 8) * RSTG + col) = __floats2half2_rn(c[mt][nt][2], c[mt][nt][3]);
            }
        }
        __syncthreads();
        const int rowg0 = blockIdx.y * HBM;
        __half* dstb = (__half*)Cm + (size_t)blockIdx.x * HBN;
#pragma unroll
        for (int i = 0; i < 16; i++) {
            int item = tid + i * 256;           // 4096 items: 128 rows x 32 d2
            int r = item >> 5, d2i = item & 31, d2 = d2i * 2;
            int tg = (rowg0 + r) & (T_ - 1);
            float4 tb = ropetab[tg * 32 + d2i];
            __half2 lo = *(__half2*)(Cs + r * RSTG + d2);
            __half2 hi = *(__half2*)(Cs + r * RSTG + d2 + 64);
            float x1a = __low2float(lo), x1b = __high2float(lo);
            float x2a = __low2float(hi), x2b = __high2float(hi);
            __half* dst = dstb + (size_t)(rowg0 + r) * N;
            *(__half2*)(dst + d2)      = __floats2half2_rn(x1a * tb.x - x2a * tb.y,
                                                           x1b * tb.x - x2b * tb.y);
            *(__half2*)(dst + d2 + 64) = __floats2half2_rn(x2a * tb.z + x1a * tb.w,
                                                           x2b * tb.z + x1b * tb.w);
        }
    } else {
        const int row_base = blockIdx.y * HBM + warp_m * 64;
        const int col_base = blockIdx.x * HBN + warp_n * 32;
#pragma unroll
        for (int mt = 0; mt < 4; mt++) {
#pragma unroll
            for (int nt = 0; nt < 4; nt++) {
                int row = row_base + mt * 16 + g;
                int col = col_base + nt * 8 + 2 * t;
                store2(Cm + (size_t)row * N + col,       c[mt][nt][0], c[mt][nt][1]);
                store2(Cm + (size_t)(row + 8) * N + col, c[mt][nt][2], c[mt][nt][3]);
            }
        }
    }
}

// ---------------- V transpose: fp16 qkv V cols -> fp16 (b,kvh,hd,t) ----------
__global__ void vtrans_h_kernel(const __half* __restrict__ qkv, __half* __restrict__ Vt) {
    __shared__ __half tile[32][34];
    const int z = blockIdx.z;
    const int b = z / NKV_;
    const int kvh = z % NKV_;
    const int t0 = blockIdx.x * 32;
    const int h0 = blockIdx.y * 32;

#pragma unroll
    for (int i = 0; i < 4; i++) {
        int tt = t0 + threadIdx.y + i * 8;
        tile[threadIdx.y + i * 8][threadIdx.x] =
            qkv[(size_t)(b * T_ + tt) * QKVN + C_ + KVD_ + kvh * HD_ + h0 + threadIdx.x];
    }
    __syncthreads();
#pragma unroll
    for (int i = 0; i < 4; i++) {
        int hd = h0 + threadIdx.y + i * 8;
        int tt = t0 + threadIdx.x;
        Vt[((size_t)(b * NKV_ + kvh) * HD_ + hd) * T_ + tt] = tile[threadIdx.x][threadIdx.y + i * 8];
    }
}

// ---------------- Flash attention: FA2-style, P in registers ------------------
#define ABM 128
#define ABN 64
#define AH_QST 136
#define AH_VST 72
#define AQ_HALVES (128 * AH_QST)
#define AK_HALVES (64 * AH_QST)
#define AV_HALVES (128 * AH_VST)
#define ATTH_SMEM_BYTES ((AQ_HALVES + 2 * AK_HALVES + 2 * AV_HALVES) * 2)  // 106496

__global__ void __launch_bounds__(256, 2) attn_h_kernel(const __half* __restrict__ QKVh,
                                                        const __half* __restrict__ Vth,
                                                        __half* __restrict__ Oh) {
    const int qt  = (int)gridDim.x - 1 - (int)blockIdx.x;
    const int h   = blockIdx.y;
    const int b   = blockIdx.z;
    const int kvh = h >> 1;

    extern __shared__ __half sh[];
    __half* Qs = sh;
    __half* Ks = Qs + AQ_HALVES;
    __half* Vs = Ks + 2 * AK_HALVES;

    const int tid  = threadIdx.x;
    const int wid  = tid >> 5;
    const int lane = tid & 31;
    const int g = lane >> 2;
    const int t = lane & 3;
    const int qrow0 = wid * 16;

    const int rowA  = lane & 15;
    const int koffA = (lane >> 4) * 8;
    const int rowB  = (lane & 7) + ((lane >> 4) << 3);
    const int koffB = ((lane >> 3) & 1) * 8;

    const int q0 = qt * ABM;
    const int jtmax = 2 * qt + 1;
    const __half* vtb = Vth + (size_t)(b * NKV_ + kvh) * HD_ * T_;
    const __half* qb  = QKVh + (size_t)(b * T_ + q0) * QKVN + h * HD_;
    const __half* kb  = QKVh + (size_t)(b * T_) * QKVN + C_ + kvh * HD_;

#pragma unroll
    for (int i = 0; i < 8; i++) {
        int v = i * 256 + tid;
        int r = v >> 4, c = v & 15;
        *(uint4*)(Qs + r * AH_QST + c * 8) = *(const uint4*)(qb + (size_t)r * QKVN + c * 8);
    }

    auto load_kv = [&](int jt, int buf) {
        const int j0 = jt * ABN;
        __half* ks = Ks + buf * AK_HALVES;
        __half* vs = Vs + buf * AV_HALVES;
#pragma unroll
        for (int i = 0; i < 4; i++) {
            int v = i * 256 + tid;
            int r = v >> 4, c = v & 15;
            cp_async16(ks + r * AH_QST + c * 8, kb + (size_t)(j0 + r) * QKVN + c * 8);
        }
#pragma unroll
        for (int i = 0; i < 4; i++) {
            int v = i * 256 + tid;
            int r = v >> 3, c = v & 7;
            cp_async16(vs + r * AH_VST + c * 8, vtb + (size_t)r * T_ + j0 + c * 8);
        }
    };

    float o[16][4];
#pragma unroll
    for (int nt = 0; nt < 16; nt++)
#pragma unroll
        for (int r = 0; r < 4; r++) o[nt][r] = 0.f;
    float m_lo = -1e30f, m_hi = -1e30f, l_lo = 0.f, l_hi = 0.f;

    load_kv(0, 0);
    CP_COMMIT();

    const float scale = 0.08838834764831845f;
    const int rl = qrow0 + g, rh = rl + 8;

    for (int jt = 0; jt <= jtmax; jt++) {
        const int cur = jt & 1;
        if (jt < jtmax) {
            load_kv(jt + 1, cur ^ 1);
            CP_COMMIT();
            CP_WAIT(1);
        } else {
            CP_WAIT(0);
        }
        __syncthreads();

        const __half* ksf = Ks + cur * AK_HALVES;
        const __half* vsf = Vs + cur * AV_HALVES;

        float s[8][4];
#pragma unroll
        for (int nt = 0; nt < 8; nt++)
#pragma unroll
            for (int r = 0; r < 4; r++) s[nt][r] = 0.f;

#pragma unroll
        for (int kk = 0; kk < HD_; kk += 16) {
            uint32_t af[4], bf[4][4];
            ldsm4(af, Qs + (qrow0 + rowA) * AH_QST + kk + koffA);
#pragma unroll
            for (int np = 0; np < 4; np++)
                ldsm4(bf[np], ksf + (np * 16 + rowB) * AH_QST + kk + koffB);
#pragma unroll
            for (int nt = 0; nt < 8; nt++)
                MMA_F16(s[nt], af, (&bf[nt >> 1][(nt & 1) * 2]));
        }

        const bool diag = (jt >= 2 * qt);
        float mxlo = -1e30f, mxhi = -1e30f;
#pragma unroll
        for (int nt = 0; nt < 8; nt++) {
            int gc0 = jt * ABN + nt * 8 + 2 * t;
            s[nt][0] *= scale; s[nt][1] *= scale;
            s[nt][2] *= scale; s[nt][3] *= scale;
            if (diag) {
                if (gc0     > q0 + rl) s[nt][0] = -1e30f;
                if (gc0 + 1 > q0 + rl) s[nt][1] = -1e30f;
                if (gc0     > q0 + rh) s[nt][2] = -1e30f;
                if (gc0 + 1 > q0 + rh) s[nt][3] = -1e30f;
            }
            mxlo = fmaxf(mxlo, fmaxf(s[nt][0], s[nt][1]));
            mxhi = fmaxf(mxhi, fmaxf(s[nt][2], s[nt][3]));
        }
        mxlo = fmaxf(mxlo, __shfl_xor_sync(0xffffffffu, mxlo, 1));
        mxlo = fmaxf(mxlo, __shfl_xor_sync(0xffffffffu, mxlo, 2));
        mxhi = fmaxf(mxhi, __shfl_xor_sync(0xffffffffu, mxhi, 1));
        mxhi = fmaxf(mxhi, __shfl_xor_sync(0xffffffffu, mxhi, 2));
        mxlo = fmaxf(mxlo, m_lo);
        mxhi = fmaxf(mxhi, m_hi);

        uint32_t ph[16];
        float sumlo = 0.f, sumhi = 0.f;
#pragma unroll
        for (int nt = 0; nt < 8; nt++) {
            float p0 = __expf(s[nt][0] - mxlo);
            float p1 = __expf(s[nt][1] - mxlo);
            float p2 = __expf(s[nt][2] - mxhi);
            float p3 = __expf(s[nt][3] - mxhi);
            __half2 plo = __floats2half2_rn(p0, p1);
            __half2 phi = __floats2half2_rn(p2, p3);
            sumlo += __low2float(plo) + __high2float(plo);
            sumhi += __low2float(phi) + __high2float(phi);
            ph[nt * 2]     = *(uint32_t*)&plo;
            ph[nt * 2 + 1] = *(uint32_t*)&phi;
        }
        sumlo += __shfl_xor_sync(0xffffffffu, sumlo, 1);
        sumlo += __shfl_xor_sync(0xffffffffu, sumlo, 2);
        sumhi += __shfl_xor_sync(0xffffffffu, sumhi, 1);
        sumhi += __shfl_xor_sync(0xffffffffu, sumhi, 2);

        float alo = __expf(m_lo - mxlo);
        float ahi = __expf(m_hi - mxhi);
        m_lo = mxlo; l_lo = l_lo * alo + sumlo;
        m_hi = mxhi; l_hi = l_hi * ahi + sumhi;
#pragma unroll
        for (int nt = 0; nt < 16; nt++) {
            o[nt][0] *= alo; o[nt][1] *= alo;
            o[nt][2] *= ahi; o[nt][3] *= ahi;
        }

#pragma unroll
        for (int kk = 0; kk < ABN; kk += 16) {
            const int j = kk >> 4;
            uint32_t a[4] = { ph[4 * j], ph[4 * j + 1], ph[4 * j + 2], ph[4 * j + 3] };
            uint32_t bf[8][4];
#pragma unroll
            for (int np = 0; np < 8; np++)
                ldsm4(bf[np], vsf + (np * 16 + rowB) * AH_VST + kk + koffB);
#pragma unroll
            for (int nt = 0; nt < 16; nt++)
                MMA_F16(o[nt], a, (&bf[nt >> 1][(nt & 1) * 2]));
        }
        __syncthreads();
    }

    float inv_lo = 1.f / l_lo;
    float inv_hi = 1.f / l_hi;
    __half* dlo = Oh + (size_t)(b * T_ + q0 + rl) * C_ + h * HD_;
    __half* dhi = Oh + (size_t)(b * T_ + q0 + rh) * C_ + h * HD_;
#pragma unroll
    for (int nt = 0; nt < 16; nt++) {
        int col = nt * 8 + 2 * t;
        *(__half2*)(dlo + col) = __floats2half2_rn(o[nt][0] * inv_lo, o[nt][1] * inv_lo);
        *(__half2*)(dhi + col) = __floats2half2_rn(o[nt][2] * inv_hi, o[nt][3] * inv_hi);
    }
}

// ---------------- launch ------------------------------------------------------
extern "C" void kernel_launch(void* const* d_in, const int* in_sizes, int n_in,
                              void* d_out, int out_size) {
    const float* x  = (const float*)d_in[0];
    const float* Wq = (const float*)d_in[1];
    const float* Wk = (const float*)d_in[2];
    const float* Wv = (const float*)d_in[3];
    const float* Wo = (const float*)d_in[4];
    float* y = (float*)d_out;

    __half *wqkvh, *worh, *qkvh, *vth, *oh;
    float4* ropetab;
    cudaGetSymbolAddress((void**)&wqkvh, g_wqkvh);
    cudaGetSymbolAddress((void**)&worh,  g_worh);
    cudaGetSymbolAddress((void**)&qkvh,  g_qkvh);
    cudaGetSymbolAddress((void**)&vth,   g_vth);
    cudaGetSymbolAddress((void**)&oh,    g_oh);
    cudaGetSymbolAddress((void**)&ropetab, g_ropetab);

    cudaFuncSetAttribute(attn_h_kernel, cudaFuncAttributeMaxDynamicSharedMemorySize,
                         ATTH_SMEM_BYTES);
    cudaFuncSetAttribute((gemm_h<float, __half, true>),
                         cudaFuncAttributeMaxDynamicSharedMemorySize, GEMMH_SMEM_BYTES);
    cudaFuncSetAttribute((gemm_h<__half, float, false>),
                         cudaFuncAttributeMaxDynamicSharedMemorySize, GEMMH_SMEM_BYTES);

    // weight fp16 conversion + rope table
    {
        size_t nthreads = ROUNDW_TOTAL4 / 4;
        round_w_kernel<<<(unsigned)((nthreads + 255) / 256), 256>>>(Wq, Wk, Wv, Wo);
        ropetab_kernel<<<(T_ * 32 + 255) / 256, 256>>>(ropetab);
    }

    // fused QKV projection: fp32 x in, fp16 out, rope fused for q/k heads
    gemm_h<float, __half, true><<<dim3(QKVN / HBN, M_ / HBM), 256, GEMMH_SMEM_BYTES>>>(
        x, wqkvh, qkvh, ropetab, M_, QKVN, C_);

    // V transpose -> fp16 (b,kvh,hd,t)
    vtrans_h_kernel<<<dim3(T_ / 32, HD_ / 32, B_ * NKV_), dim3(32, 8)>>>(qkvh, vth);

    // attention (fp16 TC, FA2 register-P, occupancy 2)
    attn_h_kernel<<<dim3(T_ / ABM, NH_, B_), 256, ATTH_SMEM_BYTES>>>(qkvh, vth, oh);

    // output projection: fp16 in, fp32 out
    gemm_h<__half, float, false><<<dim3(C_ / HBN, M_ / HBM), 256, GEMMH_SMEM_BYTES>>>(
        oh, worh, y, nullptr, M_, C_, C_);
}

// round 16
// speedup vs baseline: 1.8374x; 1.0063x over previous
#include <cuda_runtime.h>
#include <cuda_fp16.h>
#include <math.h>
#include <stdint.h>

// Problem constants
#define B_    4
#define T_    2048
#define C_    2048
#define NH_   16
#define NKV_  8
#define HD_   128
#define M_    (B_*T_)          // 8192
#define KVD_  (NKV_*HD_)       // 1024
#define QKVN  (C_ + 2*KVD_)    // 4096

// ---------------- scratch ----------------------------------------------------
__device__ __half g_wqkvh[(size_t)QKVN * C_];          // Wq|Wk|Wv fp16
__device__ __half g_worh[(size_t)C_ * C_];             // Wo fp16
__device__ __half g_qkvh[(size_t)M_ * QKVN];           // q/k (rope'd) fp16; V cols unused
__device__ __half g_vth[(size_t)B_ * NKV_ * HD_ * T_]; // V transposed fp16
__device__ __half g_oh[(size_t)M_ * C_];               // attention out fp16
__device__ float4 g_ropetab[(size_t)T_ * 32];          // (c1,s1,c2,s2) per (t, i1)

// ---------------- helpers ----------------------------------------------------
__device__ __forceinline__ void cp_async16(void* smem, const void* gmem) {
    uint32_t sa = (uint32_t)__cvta_generic_to_shared(smem);
    asm volatile("cp.async.cg.shared.global [%0], [%1], 16;\n" :: "r"(sa), "l"(gmem));
}
#define CP_COMMIT() asm volatile("cp.async.commit_group;\n" ::: "memory")
#define CP_WAIT(n)  asm volatile("cp.async.wait_group %0;\n" :: "n"(n) : "memory")

#define MMA_F16(d, a, b) \
    asm volatile("mma.sync.aligned.m16n8k16.row.col.f32.f16.f16.f32 " \
                 "{%0,%1,%2,%3}, {%4,%5,%6,%7}, {%8,%9}, {%0,%1,%2,%3};" \
                 : "+f"(d[0]), "+f"(d[1]), "+f"(d[2]), "+f"(d[3]) \
                 : "r"(a[0]), "r"(a[1]), "r"(a[2]), "r"(a[3]), "r"(b[0]), "r"(b[1]))

__device__ __forceinline__ void ldsm4(uint32_t* r, const void* p) {
    uint32_t a = (uint32_t)__cvta_generic_to_shared(p);
    asm volatile("ldmatrix.sync.aligned.m8n8.x4.shared.b16 {%0,%1,%2,%3}, [%4];"
                 : "=r"(r[0]), "=r"(r[1]), "=r"(r[2]), "=r"(r[3]) : "r"(a));
}

__device__ __forceinline__ void store2(float* p, float a, float b) {
    *(float2*)p = make_float2(a, b);
}
__device__ __forceinline__ void store2(__half* p, float a, float b) {
    *(__half2*)p = __floats2half2_rn(a, b);
}

#define L2C_ 0.20762050593046f   // log2(10000)/64

// ---------------- rope table -------------------------------------------------
__global__ void ropetab_kernel(float4* __restrict__ tab) {
    int idx = blockIdx.x * blockDim.x + threadIdx.x;
    if (idx >= T_ * 32) return;
    int t = idx >> 5, i = idx & 31;
    float inv1 = exp2f(-(float)i * L2C_);
    float inv2 = exp2f(-(float)(i + 32) * L2C_);
    float s1, c1, s2, c2;
    sincosf((float)t * inv1, &s1, &c1);
    sincosf((float)t * inv2, &s2, &c2);
    tab[idx] = make_float4(c1, s1, c2, s2);
}

// ---------------- weight fp16 conversion (MLP=4) ------------------------------
__global__ void round_w_kernel(const float* __restrict__ Wq, const float* __restrict__ Wk,
                               const float* __restrict__ Wv, const float* __restrict__ Wo) {
    const size_t NQ = (size_t)C_ * C_ / 4;
    const size_t NK = (size_t)KVD_ * C_ / 4;
    size_t j = ((size_t)blockIdx.x * blockDim.x + threadIdx.x) * 4;
    const float4* src; __half* dst; size_t off;
    if (j < NQ)                { src = (const float4*)Wq; dst = g_wqkvh; off = j; }
    else if (j < NQ + NK)      { src = (const float4*)Wk; dst = g_wqkvh + (size_t)C_ * C_; off = j - NQ; }
    else if (j < NQ + 2*NK)    { src = (const float4*)Wv; dst = g_wqkvh + (size_t)(C_ + KVD_) * C_; off = j - NQ - NK; }
    else if (j < 2*NQ + 2*NK)  { src = (const float4*)Wo; dst = g_worh;  off = j - NQ - 2*NK; }
    else return;
#pragma unroll
    for (int i = 0; i < 4; i++) {
        float4 v = src[off + i];
        *(__half2*)(dst + (off + i) * 4)     = __floats2half2_rn(v.x, v.y);
        *(__half2*)(dst + (off + i) * 4 + 2) = __floats2half2_rn(v.z, v.w);
    }
}
#define ROUNDW_TOTAL4 (2*((size_t)C_*C_/4) + 2*((size_t)KVD_*C_/4))

// ---------------- fp16 tensor-core GEMM: C[M,N] = A[M,K] * B[N,K]^T ----------
// Single barrier per K-iter: WAIT(0); sync; issue next-stage loads; compute.
// AT=float: A converted fp32->fp16 via register prefetch (distance 2) + STS.
// FUSE_EPI: bx<24 -> rope epilogue to Cm; bx>=24 -> transposed store to Vt.
#define HBM 128
#define HBN 128
#define HBK 32
#define HSTR 40   // halves; conflict-free ldmatrix
#define GEMMH_SMEM_BYTES (2 * (HBM * HSTR + HBN * HSTR) * 2)   // 40960
#define RSTG 136  // rope stage stride (halves)
#define RSTV 130  // vtrans stage stride (halves)

template <typename AT, typename OT, bool FUSE_EPI>
__global__ void __launch_bounds__(256, 2) gemm_h(const AT* __restrict__ A,
                                                 const __half* __restrict__ Bm,
                                                 OT* __restrict__ Cm,
                                                 __half* __restrict__ Vt,
                                                 const float4* __restrict__ ropetab,
                                                 int M, int N, int K) {
    extern __shared__ __half hs[];
    __half* As = hs;
    __half* Bs = hs + 2 * HBM * HSTR;

    const int tid = threadIdx.x;
    const int wid = tid >> 5;
    const int lane = tid & 31;
    const int warp_m = wid >> 2;
    const int warp_n = wid & 3;
    const int g = lane >> 2;
    const int t = lane & 3;

    const int rowA  = lane & 15;
    const int koffA = (lane >> 4) * 8;
    const int rowB  = (lane & 7) + ((lane >> 4) << 3);
    const int koffB = ((lane >> 3) & 1) * 8;

    const AT* Ag = A + (size_t)blockIdx.y * HBM * K;
    const __half* Bg = Bm + (size_t)blockIdx.x * HBN * K;

    float c[4][4][4];
#pragma unroll
    for (int mt = 0; mt < 4; mt++)
#pragma unroll
        for (int nt = 0; nt < 4; nt++)
#pragma unroll
            for (int r = 0; r < 4; r++) c[mt][nt][r] = 0.f;

    auto load_B = [&](int it, int buf) {
        int k0 = it * HBK;
        __half* bs = Bs + buf * HBN * HSTR;
#pragma unroll
        for (int i = 0; i < 2; i++) {
            int idx = i * 256 + tid;
            int r = idx >> 2, cc = idx & 3;
            cp_async16(bs + r * HSTR + cc * 8, Bg + (size_t)r * K + k0 + cc * 8);
        }
    };
    auto load_A_async = [&](int it, int buf) {   // fp16 A path
        int k0 = it * HBK;
        __half* as = As + buf * HBM * HSTR;
#pragma unroll
        for (int i = 0; i < 2; i++) {
            int idx = i * 256 + tid;
            int r = idx >> 2, cc = idx & 3;
            cp_async16(as + r * HSTR + cc * 8, (const __half*)Ag + (size_t)r * K + k0 + cc * 8);
        }
    };

    float4 ra[4];
    auto ldg_A = [&](int it) {                  // fp32 A path: LDG into registers
        int k0 = it * HBK;
#pragma unroll
        for (int i = 0; i < 2; i++) {
            int idx = i * 256 + tid;
            int r = idx >> 2, cc = idx & 3;
            const float* p = (const float*)Ag + (size_t)r * K + k0 + cc * 8;
            ra[2 * i]     = *(const float4*)p;
            ra[2 * i + 1] = *(const float4*)(p + 4);
        }
    };
    auto sts_A = [&](int buf) {                 // convert + store (consumes ra)
        __half* as = As + buf * HBM * HSTR;
#pragma unroll
        for (int i = 0; i < 2; i++) {
            int idx = i * 256 + tid;
            int r = idx >> 2, cc = idx & 3;
            __half2 h0 = __floats2half2_rn(ra[2*i].x,   ra[2*i].y);
            __half2 h1 = __floats2half2_rn(ra[2*i].z,   ra[2*i].w);
            __half2 h2 = __floats2half2_rn(ra[2*i+1].x, ra[2*i+1].y);
            __half2 h3 = __floats2half2_rn(ra[2*i+1].z, ra[2*i+1].w);
            uint4 u;
            u.x = *(uint32_t*)&h0; u.y = *(uint32_t*)&h1;
            u.z = *(uint32_t*)&h2; u.w = *(uint32_t*)&h3;
            *(uint4*)(as + r * HSTR + cc * 8) = u;
        }
    };

    constexpr bool A_F32 = (sizeof(AT) == 4);
    const int NIT = K / HBK;

    if constexpr (A_F32) {
        ldg_A(0); sts_A(0);        // stage 0 direct; visible after first sync
        ldg_A(1);                  // prefetch stage 1 into registers
        load_B(0, 0);
        CP_COMMIT();
    } else {
        load_A_async(0, 0);
        load_B(0, 0);
        CP_COMMIT();
    }

    for (int it = 0; it < NIT; ++it) {
        const int cur = it & 1;
        CP_WAIT(0);                // group(it) complete (this thread)
        __syncthreads();           // publish CTA-wide; all warps done with buf cur^1
        if (it + 1 < NIT) {
            if constexpr (A_F32) {
                sts_A(cur ^ 1);            // stage it+1 from ra
                if (it + 2 < NIT) ldg_A(it + 2);
                load_B(it + 1, cur ^ 1);
            } else {
                load_A_async(it + 1, cur ^ 1);
                load_B(it + 1, cur ^ 1);
            }
            CP_COMMIT();
        }

        const __half* as = As + cur * HBM * HSTR;
        const __half* bs = Bs + cur * HBN * HSTR;

#pragma unroll
        for (int kk = 0; kk < HBK; kk += 16) {
            uint32_t af[4][4], bf4[2][4];
#pragma unroll
            for (int mt = 0; mt < 4; mt++)
                ldsm4(af[mt], as + (warp_m * 64 + mt * 16 + rowA) * HSTR + kk + koffA);
#pragma unroll
            for (int np = 0; np < 2; np++)
                ldsm4(bf4[np], bs + (warp_n * 32 + np * 16 + rowB) * HSTR + kk + koffB);
#pragma unroll
            for (int mt = 0; mt < 4; mt++)
#pragma unroll
                for (int nt = 0; nt < 4; nt++)
                    MMA_F16(c[mt][nt], af[mt], (&bf4[nt >> 1][(nt & 1) * 2]));
        }
    }

    // ---------------- epilogue ----------------
    if (FUSE_EPI && (int)blockIdx.x < 24) {
        // q/k head block: stage, rope, store to Cm (qkvh)
        __syncthreads();                       // all warps done reading stage bufs
        __half* Cs = hs;                       // 128*136 = 17408 <= 20480 halves
#pragma unroll
        for (int mt = 0; mt < 4; mt++) {
#pragma unroll
            for (int nt = 0; nt < 4; nt++) {
                int row = warp_m * 64 + mt * 16 + g;
                int col = warp_n * 32 + nt * 8 + 2 * t;
                *(__half2*)(Cs + row * RSTG + col)       = __floats2half2_rn(c[mt][nt][0], c[mt][nt][1]);
                *(__half2*)(Cs + (row + 8) * RSTG + col) = __floats2half2_rn(c[mt][nt][2], c[mt][nt][3]);
            }
        }
        __syncthreads();
        const int rowg0 = blockIdx.y * HBM;
        __half* dstb = (__half*)Cm + (size_t)blockIdx.x * HBN;
#pragma unroll
        for (int i = 0; i < 16; i++) {
            int item = tid + i * 256;          // 4096: 128 rows x 32 d2
            int r = item >> 5, d2i = item & 31, d2 = d2i * 2;
            int tg = (rowg0 + r) & (T_ - 1);
            float4 tb = ropetab[tg * 32 + d2i];
            __half2 lo = *(__half2*)(Cs + r * RSTG + d2);
            __half2 hi = *(__half2*)(Cs + r * RSTG + d2 + 64);
            float x1a = __low2float(lo), x1b = __high2float(lo);
            float x2a = __low2float(hi), x2b = __high2float(hi);
            __half* dst = dstb + (size_t)(rowg0 + r) * N;
            *(__half2*)(dst + d2)      = __floats2half2_rn(x1a * tb.x - x2a * tb.y,
                                                           x1b * tb.x - x2b * tb.y);
            *(__half2*)(dst + d2 + 64) = __floats2half2_rn(x2a * tb.z + x1a * tb.w,
                                                           x2b * tb.z + x1b * tb.w);
        }
    } else if (FUSE_EPI) {
        // V head block: stage, store TRANSPOSED to Vt (b,kvh,hd,t)
        __syncthreads();
        __half* Cs = hs;                       // 128*130 = 16640 <= 20480 halves
#pragma unroll
        for (int mt = 0; mt < 4; mt++) {
#pragma unroll
            for (int nt = 0; nt < 4; nt++) {
                int row = warp_m * 64 + mt * 16 + g;
                int col = warp_n * 32 + nt * 8 + 2 * t;
                *(__half2*)(Cs + row * RSTV + col)       = __floats2half2_rn(c[mt][nt][0], c[mt][nt][1]);
                *(__half2*)(Cs + (row + 8) * RSTV + col) = __floats2half2_rn(c[mt][nt][2], c[mt][nt][3]);
            }
        }
        __syncthreads();
        const int kvh = (int)blockIdx.x - 24;
        const int rowg0 = blockIdx.y * HBM;
        const int b = rowg0 / T_;
        const int t0 = rowg0 & (T_ - 1);
        __half* dstb = Vt + ((size_t)(b * NKV_ + kvh) * HD_) * T_ + t0;
#pragma unroll
        for (int i = 0; i < 8; i++) {
            int item = tid + i * 256;          // 2048: 128 hd x 16 t-chunks
            int hd = item >> 4, tc = item & 15;
            __half tmp[8];
#pragma unroll
            for (int jj = 0; jj < 8; jj++)
                tmp[jj] = Cs[(tc * 8 + jj) * RSTV + hd];
            *(uint4*)(dstb + (size_t)hd * T_ + tc * 8) = *(uint4*)tmp;
        }
    } else {
        const int row_base = blockIdx.y * HBM + warp_m * 64;
        const int col_base = blockIdx.x * HBN + warp_n * 32;
#pragma unroll
        for (int mt = 0; mt < 4; mt++) {
#pragma unroll
            for (int nt = 0; nt < 4; nt++) {
                int row = row_base + mt * 16 + g;
                int col = col_base + nt * 8 + 2 * t;
                store2(Cm + (size_t)row * N + col,       c[mt][nt][0], c[mt][nt][1]);
                store2(Cm + (size_t)(row + 8) * N + col, c[mt][nt][2], c[mt][nt][3]);
            }
        }
    }
}

// ---------------- Flash attention: FA2-style, single barrier per iter --------
#define ABM 128
#define ABN 64
#define AH_QST 136
#define AH_VST 72
#define AQ_HALVES (128 * AH_QST)
#define AK_HALVES (64 * AH_QST)
#define AV_HALVES (128 * AH_VST)
#define ATTH_SMEM_BYTES ((AQ_HALVES + 2 * AK_HALVES + 2 * AV_HALVES) * 2)  // 106496

__global__ void __launch_bounds__(256, 2) attn_h_kernel(const __half* __restrict__ QKVh,
                                                        const __half* __restrict__ Vth,
                                                        __half* __restrict__ Oh) {
    const int qt  = (int)gridDim.x - 1 - (int)blockIdx.x;
    const int h   = blockIdx.y;
    const int b   = blockIdx.z;
    const int kvh = h >> 1;

    extern __shared__ __half sh[];
    __half* Qs = sh;
    __half* Ks = Qs + AQ_HALVES;
    __half* Vs = Ks + 2 * AK_HALVES;

    const int tid  = threadIdx.x;
    const int wid  = tid >> 5;
    const int lane = tid & 31;
    const int g = lane >> 2;
    const int t = lane & 3;
    const int qrow0 = wid * 16;

    const int rowA  = lane & 15;
    const int koffA = (lane >> 4) * 8;
    const int rowB  = (lane & 7) + ((lane >> 4) << 3);
    const int koffB = ((lane >> 3) & 1) * 8;

    const int q0 = qt * ABM;
    const int jtmax = 2 * qt + 1;
    const __half* vtb = Vth + (size_t)(b * NKV_ + kvh) * HD_ * T_;
    const __half* qb  = QKVh + (size_t)(b * T_ + q0) * QKVN + h * HD_;
    const __half* kb  = QKVh + (size_t)(b * T_) * QKVN + C_ + kvh * HD_;

#pragma unroll
    for (int i = 0; i < 8; i++) {
        int v = i * 256 + tid;
        int r = v >> 4, c = v & 15;
        *(uint4*)(Qs + r * AH_QST + c * 8) = *(const uint4*)(qb + (size_t)r * QKVN + c * 8);
    }

    auto load_kv = [&](int jt, int buf) {
        const int j0 = jt * ABN;
        __half* ks = Ks + buf * AK_HALVES;
        __half* vs = Vs + buf * AV_HALVES;
#pragma unroll
        for (int i = 0; i < 4; i++) {
            int v = i * 256 + tid;
            int r = v >> 4, c = v & 15;
            cp_async16(ks + r * AH_QST + c * 8, kb + (size_t)(j0 + r) * QKVN + c * 8);
        }
#pragma unroll
        for (int i = 0; i < 4; i++) {
            int v = i * 256 + tid;
            int r = v >> 3, c = v & 7;
            cp_async16(vs + r * AH_VST + c * 8, vtb + (size_t)r * T_ + j0 + c * 8);
        }
    };

    float o[16][4];
#pragma unroll
    for (int nt = 0; nt < 16; nt++)
#pragma unroll
        for (int r = 0; r < 4; r++) o[nt][r] = 0.f;
    float m_lo = -1e30f, m_hi = -1e30f, l_lo = 0.f, l_hi = 0.f;

    load_kv(0, 0);
    CP_COMMIT();

    const float scale = 0.08838834764831845f;
    const int rl = qrow0 + g, rh = rl + 8;

    for (int jt = 0; jt <= jtmax; jt++) {
        const int cur = jt & 1;
        CP_WAIT(0);               // group(jt) done (this thread)
        __syncthreads();          // publish; all warps finished with buf cur^1
        if (jt < jtmax) {
            load_kv(jt + 1, cur ^ 1);
            CP_COMMIT();
        }

        const __half* ksf = Ks + cur * AK_HALVES;
        const __half* vsf = Vs + cur * AV_HALVES;

        float s[8][4];
#pragma unroll
        for (int nt = 0; nt < 8; nt++)
#pragma unroll
            for (int r = 0; r < 4; r++) s[nt][r] = 0.f;

#pragma unroll
        for (int kk = 0; kk < HD_; kk += 16) {
            uint32_t af[4], bf[4][4];
            ldsm4(af, Qs + (qrow0 + rowA) * AH_QST + kk + koffA);
#pragma unroll
            for (int np = 0; np < 4; np++)
                ldsm4(bf[np], ksf + (np * 16 + rowB) * AH_QST + kk + koffB);
#pragma unroll
            for (int nt = 0; nt < 8; nt++)
                MMA_F16(s[nt], af, (&bf[nt >> 1][(nt & 1) * 2]));
        }

        const bool diag = (jt >= 2 * qt);
        float mxlo = -1e30f, mxhi = -1e30f;
#pragma unroll
        for (int nt = 0; nt < 8; nt++) {
            int gc0 = jt * ABN + nt * 8 + 2 * t;
            s[nt][0] *= scale; s[nt][1] *= scale;
            s[nt][2] *= scale; s[nt][3] *= scale;
            if (diag) {
                if (gc0     > q0 + rl) s[nt][0] = -1e30f;
                if (gc0 + 1 > q0 + rl) s[nt][1] = -1e30f;
                if (gc0     > q0 + rh) s[nt][2] = -1e30f;
                if (gc0 + 1 > q0 + rh) s[nt][3] = -1e30f;
            }
            mxlo = fmaxf(mxlo, fmaxf(s[nt][0], s[nt][1]));
            mxhi = fmaxf(mxhi, fmaxf(s[nt][2], s[nt][3]));
        }
        mxlo = fmaxf(mxlo, __shfl_xor_sync(0xffffffffu, mxlo, 1));
        mxlo = fmaxf(mxlo, __shfl_xor_sync(0xffffffffu, mxlo, 2));
        mxhi = fmaxf(mxhi, __shfl_xor_sync(0xffffffffu, mxhi, 1));
        mxhi = fmaxf(mxhi, __shfl_xor_sync(0xffffffffu, mxhi, 2));
        mxlo = fmaxf(mxlo, m_lo);
        mxhi = fmaxf(mxhi, m_hi);

        uint32_t ph[16];
        float sumlo = 0.f, sumhi = 0.f;
#pragma unroll
        for (int nt = 0; nt < 8; nt++) {
            float p0 = __expf(s[nt][0] - mxlo);
            float p1 = __expf(s[nt][1] - mxlo);
            float p2 = __expf(s[nt][2] - mxhi);
            float p3 = __expf(s[nt][3] - mxhi);
            __half2 plo = __floats2half2_rn(p0, p1);
            __half2 phi = __floats2half2_rn(p2, p3);
            sumlo += __low2float(plo) + __high2float(plo);
            sumhi += __low2float(phi) + __high2float(phi);
            ph[nt * 2]     = *(uint32_t*)&plo;
            ph[nt * 2 + 1] = *(uint32_t*)&phi;
        }
        sumlo += __shfl_xor_sync(0xffffffffu, sumlo, 1);
        sumlo += __shfl_xor_sync(0xffffffffu, sumlo, 2);
        sumhi += __shfl_xor_sync(0xffffffffu, sumhi, 1);
        sumhi += __shfl_xor_sync(0xffffffffu, sumhi, 2);

        float alo = __expf(m_lo - mxlo);
        float ahi = __expf(m_hi - mxhi);
        m_lo = mxlo; l_lo = l_lo * alo + sumlo;
        m_hi = mxhi; l_hi = l_hi * ahi + sumhi;
#pragma unroll
        for (int nt = 0; nt < 16; nt++) {
            o[nt][0] *= alo; o[nt][1] *= alo;
            o[nt][2] *= ahi; o[nt][3] *= ahi;
        }

#pragma unroll
        for (int kk = 0; kk < ABN; kk += 16) {
            const int j = kk >> 4;
            uint32_t a[4] = { ph[4 * j], ph[4 * j + 1], ph[4 * j + 2], ph[4 * j + 3] };
            uint32_t bf[8][4];
#pragma unroll
            for (int np = 0; np < 8; np++)
                ldsm4(bf[np], vsf + (np * 16 + rowB) * AH_VST + kk + koffB);
#pragma unroll
            for (int nt = 0; nt < 16; nt++)
                MMA_F16(o[nt], a, (&bf[nt >> 1][(nt & 1) * 2]));
        }
        // no end barrier: next iter's top barrier protects buffer reuse
    }

    float inv_lo = 1.f / l_lo;
    float inv_hi = 1.f / l_hi;
    __half* dlo = Oh + (size_t)(b * T_ + q0 + rl) * C_ + h * HD_;
    __half* dhi = Oh + (size_t)(b * T_ + q0 + rh) * C_ + h * HD_;
#pragma unroll
    for (int nt = 0; nt < 16; nt++) {
        int col = nt * 8 + 2 * t;
        *(__half2*)(dlo + col) = __floats2half2_rn(o[nt][0] * inv_lo, o[nt][1] * inv_lo);
        *(__half2*)(dhi + col) = __floats2half2_rn(o[nt][2] * inv_hi, o[nt][3] * inv_hi);
    }
}

// ---------------- launch ------------------------------------------------------
extern "C" void kernel_launch(void* const* d_in, const int* in_sizes, int n_in,
                              void* d_out, int out_size) {
    const float* x  = (const float*)d_in[0];
    const float* Wq = (const float*)d_in[1];
    const float* Wk = (const float*)d_in[2];
    const float* Wv = (const float*)d_in[3];
    const float* Wo = (const float*)d_in[4];
    float* y = (float*)d_out;

    __half *wqkvh, *worh, *qkvh, *vth, *oh;
    float4* ropetab;
    cudaGetSymbolAddress((void**)&wqkvh, g_wqkvh);
    cudaGetSymbolAddress((void**)&worh,  g_worh);
    cudaGetSymbolAddress((void**)&qkvh,  g_qkvh);
    cudaGetSymbolAddress((void**)&vth,   g_vth);
    cudaGetSymbolAddress((void**)&oh,    g_oh);
    cudaGetSymbolAddress((void**)&ropetab, g_ropetab);

    cudaFuncSetAttribute(attn_h_kernel, cudaFuncAttributeMaxDynamicSharedMemorySize,
                         ATTH_SMEM_BYTES);
    cudaFuncSetAttribute((gemm_h<float, __half, true>),
                         cudaFuncAttributeMaxDynamicSharedMemorySize, GEMMH_SMEM_BYTES);
    cudaFuncSetAttribute((gemm_h<__half, float, false>),
                         cudaFuncAttributeMaxDynamicSharedMemorySize, GEMMH_SMEM_BYTES);

    // weight fp16 conversion + rope table
    {
        size_t nthreads = ROUNDW_TOTAL4 / 4;
        round_w_kernel<<<(unsigned)((nthreads + 255) / 256), 256>>>(Wq, Wk, Wv, Wo);
        ropetab_kernel<<<(T_ * 32 + 255) / 256, 256>>>(ropetab);
    }

    // fused QKV projection: fp32 x in; rope for q/k; transposed V to g_vth
    gemm_h<float, __half, true><<<dim3(QKVN / HBN, M_ / HBM), 256, GEMMH_SMEM_BYTES>>>(
        x, wqkvh, qkvh, vth, ropetab, M_, QKVN, C_);

    // attention (fp16 TC, FA2 register-P, occupancy 2, 1 barrier/iter)
    attn_h_kernel<<<dim3(T_ / ABM, NH_, B_), 256, ATTH_SMEM_BYTES>>>(qkvh, vth, oh);

    // output projection: fp16 in, fp32 out
    gemm_h<__half, float, false><<<dim3(C_ / HBN, M_ / HBM), 256, GEMMH_SMEM_BYTES>>>(
        oh, worh, y, nullptr, nullptr, M_, C_, C_);
}